// round 1
// baseline (speedup 1.0000x reference)
#include <cuda_runtime.h>
#include <math.h>

// ---------------- problem constants ----------------
#define Bc   8
#define Sc   512
#define Tc   512
#define Dc   512
#define NHc  8
#define DHc  64
#define Lc   6
#define HIDc 2048
#define EPSc 1e-5f
#define BSc  (Bc * Sc)          // 4096 tokens (same for encoder and decoder)
#define SCALEc 0.125f           // 1/sqrt(64)

// ---------------- device scratch (no runtime allocation allowed) ----------------
__device__ float g_x[BSc * Dc];          // encoder stream / encoder output
__device__ float g_y[BSc * Dc];          // decoder stream
__device__ float g_q[BSc * Dc];
__device__ float g_k[BSc * Dc];
__device__ float g_v[BSc * Dc];
__device__ float g_attn[BSc * Dc];       // attention output pre-projection
__device__ float g_tmp[BSc * Dc];        // projection / ffn2 output
__device__ float g_hid[BSc * HIDc];      // ffn hidden
__device__ float g_scores[(size_t)Bc * NHc * Sc * Sc];  // 64 MB
__device__ unsigned char g_mx[BSc];
__device__ unsigned char g_my[BSc];

__device__ __forceinline__ float neg_inf_f() { return __int_as_float(0xff800000u); }

// ---------------- embedding + positional encoding (+ pad mask) ----------------
__global__ void embed_pe_kernel(const int* __restrict__ toks,
                                const float* __restrict__ emb,
                                float* __restrict__ out,
                                unsigned char* __restrict__ mask) {
    int pos = blockIdx.x % Sc;
    int b   = blockIdx.x / Sc;
    int tok = toks[b * Sc + pos];
    int t = threadIdx.x;                 // 256 threads
    if (t == 0) mask[b * Sc + pos] = (tok == 0) ? 1 : 0;
    const float c = -logf(10000.0f) / (float)Dc;
    size_t base = ((size_t)b * Sc + pos) * Dc;
    #pragma unroll
    for (int d = t; d < Dc; d += 256) {
        int i = d >> 1;
        float freq = __expf((float)(2 * i) * c);
        float ang  = (float)pos * freq;
        float pe   = (d & 1) ? cosf(ang) : sinf(ang);
        out[base + d] = emb[(size_t)tok * Dc + d] + pe;
    }
}

// ---------------- SGEMM: C[M,N] = A[M,K] @ W[K,N] + bias[N], optional relu ----------------
// 64x64 tile, 256 threads, 4x4 per thread, K-tile 16. M,N,K all multiples of 64/16 here.
template<bool RELU>
__global__ void sgemm_bias(const float* __restrict__ A, const float* __restrict__ W,
                           const float* __restrict__ bias, float* __restrict__ C,
                           int M, int N, int K) {
    __shared__ float As[16][64];
    __shared__ float Bs[16][64];
    int tid = threadIdx.x;
    int tm = tid >> 4, tn = tid & 15;
    int row0 = blockIdx.y * 64, col0 = blockIdx.x * 64;
    float acc[4][4] = {};
    for (int k0 = 0; k0 < K; k0 += 16) {
        {   // A tile: 64 rows x 16 k, transposed into As[kk][mm]
            int mm = tid >> 2;
            int kk = (tid & 3) * 4;
            float4 a4 = *reinterpret_cast<const float4*>(&A[(size_t)(row0 + mm) * K + k0 + kk]);
            As[kk + 0][mm] = a4.x; As[kk + 1][mm] = a4.y;
            As[kk + 2][mm] = a4.z; As[kk + 3][mm] = a4.w;
        }
        {   // W tile: 16 k x 64 cols
            int kk = tid >> 4;
            int nn = (tid & 15) * 4;
            float4 b4 = *reinterpret_cast<const float4*>(&W[(size_t)(k0 + kk) * N + col0 + nn]);
            *reinterpret_cast<float4*>(&Bs[kk][nn]) = b4;
        }
        __syncthreads();
        #pragma unroll
        for (int kk = 0; kk < 16; ++kk) {
            float a[4], bb[4];
            #pragma unroll
            for (int i = 0; i < 4; i++) a[i]  = As[kk][tm * 4 + i];
            #pragma unroll
            for (int j = 0; j < 4; j++) bb[j] = Bs[kk][tn * 4 + j];
            #pragma unroll
            for (int i = 0; i < 4; i++)
                #pragma unroll
                for (int j = 0; j < 4; j++)
                    acc[i][j] = fmaf(a[i], bb[j], acc[i][j]);
        }
        __syncthreads();
    }
    #pragma unroll
    for (int i = 0; i < 4; i++) {
        int row = row0 + tm * 4 + i;
        #pragma unroll
        for (int j = 0; j < 4; j++) {
            int col = col0 + tn * 4 + j;
            float v = acc[i][j] + bias[col];
            if (RELU) v = fmaxf(v, 0.0f);
            C[(size_t)row * N + col] = v;
        }
    }
}

// ---------------- attention scores: S[b,h,qi,ki] = scale * q.k, with masking ----------------
// grid: (Sc/64, Sc/64, B*NH), 256 threads, same 64x64/4x4 scheme, K = DH = 64
__global__ void qk_scores(const float* __restrict__ q, const float* __restrict__ k,
                          const unsigned char* __restrict__ mq,
                          const unsigned char* __restrict__ mk,
                          float* __restrict__ scores, int causal) {
    int bh = blockIdx.z;
    int b = bh / NHc, h = bh % NHc;
    const float* Q  = q + (size_t)b * Sc * Dc + h * DHc;
    const float* Kp = k + (size_t)b * Sc * Dc + h * DHc;
    float* Sout = scores + (size_t)bh * Sc * Sc;
    __shared__ float Qs[16][64];
    __shared__ float Ks[16][64];
    int tid = threadIdx.x;
    int tm = tid >> 4, tn = tid & 15;
    int row0 = blockIdx.y * 64, col0 = blockIdx.x * 64;
    float acc[4][4] = {};
    for (int k0 = 0; k0 < DHc; k0 += 16) {
        int mm = tid >> 2;
        int kk = (tid & 3) * 4;
        float4 a4 = *reinterpret_cast<const float4*>(&Q[(size_t)(row0 + mm) * Dc + k0 + kk]);
        Qs[kk + 0][mm] = a4.x; Qs[kk + 1][mm] = a4.y; Qs[kk + 2][mm] = a4.z; Qs[kk + 3][mm] = a4.w;
        float4 b4 = *reinterpret_cast<const float4*>(&Kp[(size_t)(col0 + mm) * Dc + k0 + kk]);
        Ks[kk + 0][mm] = b4.x; Ks[kk + 1][mm] = b4.y; Ks[kk + 2][mm] = b4.z; Ks[kk + 3][mm] = b4.w;
        __syncthreads();
        #pragma unroll
        for (int kk2 = 0; kk2 < 16; ++kk2) {
            float a[4], bb[4];
            #pragma unroll
            for (int i = 0; i < 4; i++) a[i]  = Qs[kk2][tm * 4 + i];
            #pragma unroll
            for (int j = 0; j < 4; j++) bb[j] = Ks[kk2][tn * 4 + j];
            #pragma unroll
            for (int i = 0; i < 4; i++)
                #pragma unroll
                for (int j = 0; j < 4; j++)
                    acc[i][j] = fmaf(a[i], bb[j], acc[i][j]);
        }
        __syncthreads();
    }
    #pragma unroll
    for (int i = 0; i < 4; i++) {
        int qi = row0 + tm * 4 + i;
        bool mrow = mq[b * Sc + qi] != 0;
        #pragma unroll
        for (int j = 0; j < 4; j++) {
            int ki = col0 + tn * 4 + j;
            bool m = mrow || (mk[b * Sc + ki] != 0) || (causal && ki > qi);
            Sout[(size_t)qi * Sc + ki] = m ? neg_inf_f() : acc[i][j] * SCALEc;
        }
    }
}

// ---------------- row softmax over S=512, fully-masked rows -> 0 ----------------
__global__ void softmax_rows(float* __restrict__ scores) {
    size_t row = blockIdx.x;
    float* p = scores + row * Sc;
    int t = threadIdx.x;                 // 256
    float v0 = p[t], v1 = p[t + 256];
    __shared__ float red[256];
    red[t] = fmaxf(v0, v1);
    __syncthreads();
    for (int s = 128; s > 0; s >>= 1) { if (t < s) red[t] = fmaxf(red[t], red[t + s]); __syncthreads(); }
    float rmax = red[0];
    __syncthreads();
    float e0, e1;
    if (rmax == neg_inf_f()) { e0 = 0.0f; e1 = 0.0f; }
    else { e0 = __expf(v0 - rmax); e1 = __expf(v1 - rmax); }
    red[t] = e0 + e1;
    __syncthreads();
    for (int s = 128; s > 0; s >>= 1) { if (t < s) red[t] += red[t + s]; __syncthreads(); }
    float rsum = red[0];
    float inv = (rsum > 0.0f) ? 1.0f / rsum : 0.0f;
    p[t] = e0 * inv;
    p[t + 256] = e1 * inv;
}

// ---------------- attention @ V: O[b,qi,h,:] = A[qi,:] @ V[:, :] ----------------
// grid: (1, Sc/64, B*NH); M=512, N=DH=64, K=512
__global__ void av_kernel(const float* __restrict__ scores, const float* __restrict__ v,
                          float* __restrict__ o) {
    int bh = blockIdx.z;
    int b = bh / NHc, h = bh % NHc;
    const float* A = scores + (size_t)bh * Sc * Sc;
    const float* V = v + (size_t)b * Sc * Dc + h * DHc;
    float* O = o + (size_t)b * Sc * Dc + h * DHc;
    __shared__ float As[16][64];
    __shared__ float Vs[16][64];
    int tid = threadIdx.x;
    int tm = tid >> 4, tn = tid & 15;
    int row0 = blockIdx.y * 64;
    float acc[4][4] = {};
    for (int k0 = 0; k0 < Sc; k0 += 16) {
        {
            int mm = tid >> 2;
            int kk = (tid & 3) * 4;
            float4 a4 = *reinterpret_cast<const float4*>(&A[(size_t)(row0 + mm) * Sc + k0 + kk]);
            As[kk + 0][mm] = a4.x; As[kk + 1][mm] = a4.y; As[kk + 2][mm] = a4.z; As[kk + 3][mm] = a4.w;
        }
        {
            int kk = tid >> 4;
            int nn = (tid & 15) * 4;
            float4 b4 = *reinterpret_cast<const float4*>(&V[(size_t)(k0 + kk) * Dc + nn]);
            *reinterpret_cast<float4*>(&Vs[kk][nn]) = b4;
        }
        __syncthreads();
        #pragma unroll
        for (int kk2 = 0; kk2 < 16; ++kk2) {
            float a[4], bb[4];
            #pragma unroll
            for (int i = 0; i < 4; i++) a[i]  = As[kk2][tm * 4 + i];
            #pragma unroll
            for (int j = 0; j < 4; j++) bb[j] = Vs[kk2][tn * 4 + j];
            #pragma unroll
            for (int i = 0; i < 4; i++)
                #pragma unroll
                for (int j = 0; j < 4; j++)
                    acc[i][j] = fmaf(a[i], bb[j], acc[i][j]);
        }
        __syncthreads();
    }
    #pragma unroll
    for (int i = 0; i < 4; i++)
        #pragma unroll
        for (int j = 0; j < 4; j++)
            O[(size_t)(row0 + tm * 4 + i) * Dc + tn * 4 + j] = acc[i][j];
}

// ---------------- out = LayerNorm(a + b) * gamma + beta (row-wise, D=512) ----------------
__global__ void add_ln_kernel(const float* __restrict__ a, const float* __restrict__ bsrc,
                              const float* __restrict__ gamma, const float* __restrict__ beta,
                              float* __restrict__ out) {
    size_t row = blockIdx.x;
    int t = threadIdx.x;                 // 256, 2 elems each
    size_t base = row * Dc;
    float x0 = a[base + t]       + bsrc[base + t];
    float x1 = a[base + t + 256] + bsrc[base + t + 256];
    __shared__ float red[256];
    red[t] = x0 + x1;
    __syncthreads();
    for (int s = 128; s > 0; s >>= 1) { if (t < s) red[t] += red[t + s]; __syncthreads(); }
    float mu = red[0] * (1.0f / Dc);
    __syncthreads();
    float d0 = x0 - mu, d1 = x1 - mu;
    red[t] = d0 * d0 + d1 * d1;
    __syncthreads();
    for (int s = 128; s > 0; s >>= 1) { if (t < s) red[t] += red[t + s]; __syncthreads(); }
    float inv = rsqrtf(red[0] * (1.0f / Dc) + EPSc);
    out[base + t]       = d0 * inv * gamma[t]       + beta[t];
    out[base + t + 256] = d1 * inv * gamma[t + 256] + beta[t + 256];
}

// ---------------- host orchestration ----------------
static void run_mha(const float* xq, const float* xkv,
                    const unsigned char* mq, const unsigned char* mk, int causal,
                    const float* w, const float* b,   // [4,D,D], [4,D]
                    float* qp, float* kp, float* vp, float* attnp, float* scoresp,
                    float* outp) {
    dim3 blk(256);
    dim3 gproj(Dc / 64, BSc / 64);
    sgemm_bias<false><<<gproj, blk>>>(xq,  w + 0 * Dc * Dc, b + 0 * Dc, qp, BSc, Dc, Dc);
    sgemm_bias<false><<<gproj, blk>>>(xkv, w + 1 * Dc * Dc, b + 1 * Dc, kp, BSc, Dc, Dc);
    sgemm_bias<false><<<gproj, blk>>>(xkv, w + 2 * Dc * Dc, b + 2 * Dc, vp, BSc, Dc, Dc);
    dim3 gqk(Sc / 64, Sc / 64, Bc * NHc);
    qk_scores<<<gqk, blk>>>(qp, kp, mq, mk, scoresp, causal);
    softmax_rows<<<Bc * NHc * Sc, blk>>>(scoresp);
    dim3 gav(1, Sc / 64, Bc * NHc);
    av_kernel<<<gav, blk>>>(scoresp, vp, attnp);
    sgemm_bias<false><<<gproj, blk>>>(attnp, w + 3 * Dc * Dc, b + 3 * Dc, outp, BSc, Dc, Dc);
}

extern "C" void kernel_launch(void* const* d_in, const int* in_sizes, int n_in,
                              void* d_out, int out_size) {
    const int*   inputs  = (const int*)d_in[0];
    const int*   outputs = (const int*)d_in[1];
    const float* emi = (const float*)d_in[2];
    const float* emo = (const float*)d_in[3];
    const float* enc_attn_w = (const float*)d_in[4];
    const float* enc_attn_b = (const float*)d_in[5];
    const float* enc_ln     = (const float*)d_in[6];
    const float* enc_ffn_w1 = (const float*)d_in[7];
    const float* enc_ffn_b1 = (const float*)d_in[8];
    const float* enc_ffn_w2 = (const float*)d_in[9];
    const float* enc_ffn_b2 = (const float*)d_in[10];
    const float* dec_self_w  = (const float*)d_in[11];
    const float* dec_self_b  = (const float*)d_in[12];
    const float* dec_cross_w = (const float*)d_in[13];
    const float* dec_cross_b = (const float*)d_in[14];
    const float* dec_ln      = (const float*)d_in[15];
    const float* dec_ffn_w1 = (const float*)d_in[16];
    const float* dec_ffn_b1 = (const float*)d_in[17];
    const float* dec_ffn_w2 = (const float*)d_in[18];
    const float* dec_ffn_b2 = (const float*)d_in[19];

    float *xp, *yp, *qp, *kp, *vp, *attnp, *tmpp, *hidp, *scoresp;
    unsigned char *mxp, *myp;
    cudaGetSymbolAddress((void**)&xp, g_x);
    cudaGetSymbolAddress((void**)&yp, g_y);
    cudaGetSymbolAddress((void**)&qp, g_q);
    cudaGetSymbolAddress((void**)&kp, g_k);
    cudaGetSymbolAddress((void**)&vp, g_v);
    cudaGetSymbolAddress((void**)&attnp, g_attn);
    cudaGetSymbolAddress((void**)&tmpp, g_tmp);
    cudaGetSymbolAddress((void**)&hidp, g_hid);
    cudaGetSymbolAddress((void**)&scoresp, g_scores);
    cudaGetSymbolAddress((void**)&mxp, g_mx);
    cudaGetSymbolAddress((void**)&myp, g_my);

    dim3 blk(256);
    dim3 gproj(Dc / 64, BSc / 64);
    dim3 gffn1(HIDc / 64, BSc / 64);

    // Embeddings (+ pad masks)
    embed_pe_kernel<<<BSc, blk>>>(inputs,  emi, xp, mxp);
    embed_pe_kernel<<<BSc, blk>>>(outputs, emo, yp, myp);

    // ---------------- encoder ----------------
    for (int l = 0; l < Lc; ++l) {
        const float* aw = enc_attn_w + (size_t)l * 4 * Dc * Dc;
        const float* ab = enc_attn_b + (size_t)l * 4 * Dc;
        run_mha(xp, xp, mxp, mxp, /*causal=*/0, aw, ab, qp, kp, vp, attnp, scoresp, tmpp);
        const float* ln0 = enc_ln + (((size_t)l * 2 + 0) * 2) * Dc;
        add_ln_kernel<<<BSc, blk>>>(xp, tmpp, ln0, ln0 + Dc, xp);
        sgemm_bias<true ><<<gffn1, blk>>>(xp, enc_ffn_w1 + (size_t)l * Dc * HIDc,
                                          enc_ffn_b1 + (size_t)l * HIDc, hidp, BSc, HIDc, Dc);
        sgemm_bias<false><<<gproj, blk>>>(hidp, enc_ffn_w2 + (size_t)l * HIDc * Dc,
                                          enc_ffn_b2 + (size_t)l * Dc, tmpp, BSc, Dc, HIDc);
        const float* ln1 = enc_ln + (((size_t)l * 2 + 1) * 2) * Dc;
        add_ln_kernel<<<BSc, blk>>>(xp, tmpp, ln1, ln1 + Dc, xp);
    }

    // ---------------- decoder ----------------
    float* fout = (float*)d_out;
    for (int l = 0; l < Lc; ++l) {
        // self-attention (causal + pad)
        const float* sw = dec_self_w + (size_t)l * 4 * Dc * Dc;
        const float* sb = dec_self_b + (size_t)l * 4 * Dc;
        run_mha(yp, yp, myp, myp, /*causal=*/1, sw, sb, qp, kp, vp, attnp, scoresp, tmpp);
        const float* ln0 = dec_ln + (((size_t)l * 3 + 0) * 2) * Dc;
        add_ln_kernel<<<BSc, blk>>>(yp, tmpp, ln0, ln0 + Dc, yp);

        // cross-attention (q from y, kv from encoder output x)
        const float* cw = dec_cross_w + (size_t)l * 4 * Dc * Dc;
        const float* cb = dec_cross_b + (size_t)l * 4 * Dc;
        run_mha(yp, xp, myp, mxp, /*causal=*/0, cw, cb, qp, kp, vp, attnp, scoresp, tmpp);
        const float* ln1 = dec_ln + (((size_t)l * 3 + 1) * 2) * Dc;
        add_ln_kernel<<<BSc, blk>>>(yp, tmpp, ln1, ln1 + Dc, yp);

        // FFN
        sgemm_bias<true ><<<gffn1, blk>>>(yp, dec_ffn_w1 + (size_t)l * Dc * HIDc,
                                          dec_ffn_b1 + (size_t)l * HIDc, hidp, BSc, HIDc, Dc);
        sgemm_bias<false><<<gproj, blk>>>(hidp, dec_ffn_w2 + (size_t)l * HIDc * Dc,
                                          dec_ffn_b2 + (size_t)l * Dc, tmpp, BSc, Dc, HIDc);
        const float* ln2 = dec_ln + (((size_t)l * 3 + 2) * 2) * Dc;
        // last layer's final LN writes straight into d_out
        float* dst = (l == Lc - 1) ? fout : yp;
        add_ln_kernel<<<BSc, blk>>>(yp, tmpp, ln2, ln2 + Dc, dst);
    }
    (void)in_sizes; (void)n_in; (void)out_size;
}

// round 3
// speedup vs baseline: 1.7207x; 1.7207x over previous
#include <cuda_runtime.h>
#include <math.h>
#include <cstdint>

// ---------------- problem constants ----------------
#define Bc   8
#define Sc   512
#define Dc   512
#define NHc  8
#define DHc  64
#define Lc   6
#define HIDc 2048
#define EPSc 1e-5f
#define BSc  (Bc * Sc)          // 4096 tokens
#define SCALEc 0.125f           // 1/sqrt(64)

// ---------------- device scratch ----------------
__device__ float g_x[BSc * Dc];
__device__ float g_y[BSc * Dc];
__device__ float g_q[BSc * Dc];
__device__ float g_k[BSc * Dc];
__device__ float g_v[BSc * Dc];
__device__ float g_attn[BSc * Dc];
__device__ float g_tmp[BSc * Dc];
__device__ float g_hid[BSc * HIDc];
__device__ float g_scores[(size_t)Bc * NHc * Sc * Sc];
__device__ unsigned char g_mx[BSc];
__device__ unsigned char g_my[BSc];
// transposed (tf32-rounded) weights: [N][K]
__device__ float g_wt_enc_attn[Lc * 4 * Dc * Dc];
__device__ float g_wt_dec_self[Lc * 4 * Dc * Dc];
__device__ float g_wt_dec_cross[Lc * 4 * Dc * Dc];
__device__ float g_wt_enc_f1[Lc * Dc * HIDc];
__device__ float g_wt_enc_f2[Lc * Dc * HIDc];
__device__ float g_wt_dec_f1[Lc * Dc * HIDc];
__device__ float g_wt_dec_f2[Lc * Dc * HIDc];

__device__ __forceinline__ float neg_inf_f() { return __int_as_float(0xff800000u); }

__device__ __forceinline__ uint32_t round_tf32(float v) {
    uint32_t u; asm("cvt.rna.tf32.f32 %0, %1;" : "=r"(u) : "f"(v)); return u;
}

// mma.sync m16n8k8 tf32 (sm_80+ family-compatible; NO tcgen05 — ptxas targets sm_103 non-'a')
__device__ __forceinline__ void mma_16n8k8(float c[4], const uint32_t a[4], const uint32_t b[2]) {
    asm volatile(
        "mma.sync.aligned.m16n8k8.row.col.f32.tf32.tf32.f32 "
        "{%0,%1,%2,%3}, {%4,%5,%6,%7}, {%8,%9}, {%0,%1,%2,%3};"
        : "+f"(c[0]), "+f"(c[1]), "+f"(c[2]), "+f"(c[3])
        : "r"(a[0]), "r"(a[1]), "r"(a[2]), "r"(a[3]), "r"(b[0]), "r"(b[1]));
}

// ---------------- weight transpose (with tf32 rounding) ----------------
__global__ void transpose_tf32(const float* __restrict__ in, float* __restrict__ out,
                               int R, int C) {
    __shared__ float tile[32][33];
    const float* src = in + (size_t)blockIdx.z * R * C;
    float* dst = out + (size_t)blockIdx.z * R * C;
    int c0 = blockIdx.x * 32, r0 = blockIdx.y * 32;
    int tx = threadIdx.x, ty = threadIdx.y;          // 32 x 8
    #pragma unroll
    for (int i = 0; i < 32; i += 8)
        tile[ty + i][tx] = src[(size_t)(r0 + ty + i) * C + c0 + tx];
    __syncthreads();
    #pragma unroll
    for (int i = 0; i < 32; i += 8) {
        float v = tile[tx][ty + i];
        dst[(size_t)(c0 + ty + i) * R + r0 + tx] = __uint_as_float(round_tf32(v));
    }
}

// ---------------- tf32 mma GEMM: C[M,N] = A[M,K] @ BT[N,K]^T + bias ----------------
// 128x128 CTA tile, 8 warps (2 M x 4 N), warp tile 64x32, K-chunk 32.
#define PADK 36   // (row*36+k)%32 == (row*4+k)%32 -> conflict-free fragment loads

template<bool RELU>
__global__ void __launch_bounds__(256) gemm_mma(const float* __restrict__ A,
                                                const float* __restrict__ BT,
                                                const float* __restrict__ bias,
                                                float* __restrict__ C,
                                                int M, int N, int K) {
    __shared__ uint32_t As[128 * PADK];
    __shared__ uint32_t Bs[128 * PADK];
    int tid = threadIdx.x;
    int lane = tid & 31, wid = tid >> 5;
    int wm = wid & 1;           // 0..1  -> 64 rows each
    int wn = wid >> 1;          // 0..3  -> 32 cols each
    int row0 = blockIdx.y * 128, col0 = blockIdx.x * 128;
    int g = lane >> 2, tg = lane & 3;     // groupID, thread-in-group

    float acc[4][4][4];
    #pragma unroll
    for (int mi = 0; mi < 4; mi++)
        #pragma unroll
        for (int ni = 0; ni < 4; ni++)
            #pragma unroll
            for (int r = 0; r < 4; r++) acc[mi][ni][r] = 0.0f;

    for (int k0 = 0; k0 < K; k0 += 32) {
        // ---- load A/B 128x32 tiles (tf32-rounded), coalesced float4 ----
        #pragma unroll
        for (int i = 0; i < 4; ++i) {
            int idx = tid + i * 256;                 // 0..1023
            int r = idx >> 3, cc = (idx & 7) * 4;
            float4 va = *reinterpret_cast<const float4*>(&A[(size_t)(row0 + r) * K + k0 + cc]);
            uint4 ua = make_uint4(round_tf32(va.x), round_tf32(va.y),
                                  round_tf32(va.z), round_tf32(va.w));
            *reinterpret_cast<uint4*>(&As[r * PADK + cc]) = ua;
            float4 vb = *reinterpret_cast<const float4*>(&BT[(size_t)(col0 + r) * K + k0 + cc]);
            uint4 ub = make_uint4(round_tf32(vb.x), round_tf32(vb.y),
                                  round_tf32(vb.z), round_tf32(vb.w));
            *reinterpret_cast<uint4*>(&Bs[r * PADK + cc]) = ub;
        }
        __syncthreads();

        #pragma unroll
        for (int ki = 0; ki < 4; ++ki) {
            int ak = ki * 8 + tg;
            uint32_t afr[4][4];
            #pragma unroll
            for (int mi = 0; mi < 4; mi++) {
                int r = wm * 64 + mi * 16 + g;
                afr[mi][0] = As[(r)     * PADK + ak];
                afr[mi][1] = As[(r + 8) * PADK + ak];
                afr[mi][2] = As[(r)     * PADK + ak + 4];
                afr[mi][3] = As[(r + 8) * PADK + ak + 4];
            }
            uint32_t bfr[4][2];
            #pragma unroll
            for (int ni = 0; ni < 4; ni++) {
                int n = wn * 32 + ni * 8 + g;
                bfr[ni][0] = Bs[n * PADK + ak];       // k = ki*8+tg
                bfr[ni][1] = Bs[n * PADK + ak + 4];
            }
            #pragma unroll
            for (int mi = 0; mi < 4; mi++)
                #pragma unroll
                for (int ni = 0; ni < 4; ni++)
                    mma_16n8k8(acc[mi][ni], afr[mi], bfr[ni]);
        }
        __syncthreads();
    }

    // ---- epilogue: bias (+relu), direct global stores ----
    #pragma unroll
    for (int mi = 0; mi < 4; mi++) {
        int r0r = row0 + wm * 64 + mi * 16 + g;
        #pragma unroll
        for (int ni = 0; ni < 4; ni++) {
            int cb = col0 + wn * 32 + ni * 8 + tg * 2;
            float b0 = bias[cb], b1 = bias[cb + 1];
            float v0 = acc[mi][ni][0] + b0, v1 = acc[mi][ni][1] + b1;
            float v2 = acc[mi][ni][2] + b0, v3 = acc[mi][ni][3] + b1;
            if (RELU) { v0 = fmaxf(v0, 0.f); v1 = fmaxf(v1, 0.f);
                        v2 = fmaxf(v2, 0.f); v3 = fmaxf(v3, 0.f); }
            *reinterpret_cast<float2*>(&C[(size_t)(r0r)     * N + cb]) = make_float2(v0, v1);
            *reinterpret_cast<float2*>(&C[(size_t)(r0r + 8) * N + cb]) = make_float2(v2, v3);
        }
    }
}

// ---------------- embedding + positional encoding (+ pad mask) ----------------
__global__ void embed_pe_kernel(const int* __restrict__ toks,
                                const float* __restrict__ emb,
                                float* __restrict__ out,
                                unsigned char* __restrict__ mask) {
    int pos = blockIdx.x % Sc;
    int b   = blockIdx.x / Sc;
    int tok = toks[b * Sc + pos];
    int t = threadIdx.x;
    if (t == 0) mask[b * Sc + pos] = (tok == 0) ? 1 : 0;
    const float c = -logf(10000.0f) / (float)Dc;
    size_t base = ((size_t)b * Sc + pos) * Dc;
    #pragma unroll
    for (int d = t; d < Dc; d += 256) {
        int i = d >> 1;
        float freq = __expf((float)(2 * i) * c);
        float ang  = (float)pos * freq;
        float pe   = (d & 1) ? cosf(ang) : sinf(ang);
        out[base + d] = emb[(size_t)tok * Dc + d] + pe;
    }
}

// ---------------- attention scores (fp32): S = scale * Q @ K^T, masked ----------------
__global__ void qk_scores(const float* __restrict__ q, const float* __restrict__ k,
                          const unsigned char* __restrict__ mq,
                          const unsigned char* __restrict__ mk,
                          float* __restrict__ scores, int causal) {
    int bh = blockIdx.z;
    int b = bh / NHc, h = bh % NHc;
    const float* Q  = q + (size_t)b * Sc * Dc + h * DHc;
    const float* Kp = k + (size_t)b * Sc * Dc + h * DHc;
    float* Sout = scores + (size_t)bh * Sc * Sc;
    __shared__ float Qs[16][64];
    __shared__ float Ks[16][64];
    int tid = threadIdx.x;
    int tm = tid >> 4, tn = tid & 15;
    int row0 = blockIdx.y * 64, col0 = blockIdx.x * 64;
    float acc[4][4] = {};
    for (int k0 = 0; k0 < DHc; k0 += 16) {
        int mm = tid >> 2;
        int kk = (tid & 3) * 4;
        float4 a4 = *reinterpret_cast<const float4*>(&Q[(size_t)(row0 + mm) * Dc + k0 + kk]);
        Qs[kk + 0][mm] = a4.x; Qs[kk + 1][mm] = a4.y; Qs[kk + 2][mm] = a4.z; Qs[kk + 3][mm] = a4.w;
        float4 b4 = *reinterpret_cast<const float4*>(&Kp[(size_t)(col0 + mm) * Dc + k0 + kk]);
        Ks[kk + 0][mm] = b4.x; Ks[kk + 1][mm] = b4.y; Ks[kk + 2][mm] = b4.z; Ks[kk + 3][mm] = b4.w;
        __syncthreads();
        #pragma unroll
        for (int kk2 = 0; kk2 < 16; ++kk2) {
            float a[4], bb[4];
            #pragma unroll
            for (int i = 0; i < 4; i++) a[i]  = Qs[kk2][tm * 4 + i];
            #pragma unroll
            for (int j = 0; j < 4; j++) bb[j] = Ks[kk2][tn * 4 + j];
            #pragma unroll
            for (int i = 0; i < 4; i++)
                #pragma unroll
                for (int j = 0; j < 4; j++)
                    acc[i][j] = fmaf(a[i], bb[j], acc[i][j]);
        }
        __syncthreads();
    }
    #pragma unroll
    for (int i = 0; i < 4; i++) {
        int qi = row0 + tm * 4 + i;
        bool mrow = mq[b * Sc + qi] != 0;
        #pragma unroll
        for (int j = 0; j < 4; j++) {
            int ki = col0 + tn * 4 + j;
            bool m = mrow || (mk[b * Sc + ki] != 0) || (causal && ki > qi);
            Sout[(size_t)qi * Sc + ki] = m ? neg_inf_f() : acc[i][j] * SCALEc;
        }
    }
}

// ---------------- row softmax over 512, fully-masked rows -> 0 ----------------
__global__ void softmax_rows(float* __restrict__ scores) {
    size_t row = blockIdx.x;
    float* p = scores + row * Sc;
    int t = threadIdx.x;
    float v0 = p[t], v1 = p[t + 256];
    __shared__ float red[256];
    red[t] = fmaxf(v0, v1);
    __syncthreads();
    for (int s = 128; s > 0; s >>= 1) { if (t < s) red[t] = fmaxf(red[t], red[t + s]); __syncthreads(); }
    float rmax = red[0];
    __syncthreads();
    float e0, e1;
    if (rmax == neg_inf_f()) { e0 = 0.0f; e1 = 0.0f; }
    else { e0 = __expf(v0 - rmax); e1 = __expf(v1 - rmax); }
    red[t] = e0 + e1;
    __syncthreads();
    for (int s = 128; s > 0; s >>= 1) { if (t < s) red[t] += red[t + s]; __syncthreads(); }
    float rsum = red[0];
    float inv = (rsum > 0.0f) ? 1.0f / rsum : 0.0f;
    p[t] = e0 * inv;
    p[t + 256] = e1 * inv;
}

// ---------------- attention @ V (fp32) ----------------
__global__ void av_kernel(const float* __restrict__ scores, const float* __restrict__ v,
                          float* __restrict__ o) {
    int bh = blockIdx.z;
    int b = bh / NHc, h = bh % NHc;
    const float* A = scores + (size_t)bh * Sc * Sc;
    const float* V = v + (size_t)b * Sc * Dc + h * DHc;
    float* O = o + (size_t)b * Sc * Dc + h * DHc;
    __shared__ float As[16][64];
    __shared__ float Vs[16][64];
    int tid = threadIdx.x;
    int tm = tid >> 4, tn = tid & 15;
    int row0 = blockIdx.y * 64;
    float acc[4][4] = {};
    for (int k0 = 0; k0 < Sc; k0 += 16) {
        {
            int mm = tid >> 2;
            int kk = (tid & 3) * 4;
            float4 a4 = *reinterpret_cast<const float4*>(&A[(size_t)(row0 + mm) * Sc + k0 + kk]);
            As[kk + 0][mm] = a4.x; As[kk + 1][mm] = a4.y; As[kk + 2][mm] = a4.z; As[kk + 3][mm] = a4.w;
        }
        {
            int kk = tid >> 4;
            int nn = (tid & 15) * 4;
            float4 b4 = *reinterpret_cast<const float4*>(&V[(size_t)(k0 + kk) * Dc + nn]);
            *reinterpret_cast<float4*>(&Vs[kk][nn]) = b4;
        }
        __syncthreads();
        #pragma unroll
        for (int kk2 = 0; kk2 < 16; ++kk2) {
            float a[4], bb[4];
            #pragma unroll
            for (int i = 0; i < 4; i++) a[i]  = As[kk2][tm * 4 + i];
            #pragma unroll
            for (int j = 0; j < 4; j++) bb[j] = Vs[kk2][tn * 4 + j];
            #pragma unroll
            for (int i = 0; i < 4; i++)
                #pragma unroll
                for (int j = 0; j < 4; j++)
                    acc[i][j] = fmaf(a[i], bb[j], acc[i][j]);
        }
        __syncthreads();
    }
    #pragma unroll
    for (int i = 0; i < 4; i++)
        #pragma unroll
        for (int j = 0; j < 4; j++)
            O[(size_t)(row0 + tm * 4 + i) * Dc + tn * 4 + j] = acc[i][j];
}

// ---------------- out = LayerNorm(a + b) * gamma + beta ----------------
__global__ void add_ln_kernel(const float* __restrict__ a, const float* __restrict__ bsrc,
                              const float* __restrict__ gamma, const float* __restrict__ beta,
                              float* __restrict__ out) {
    size_t row = blockIdx.x;
    int t = threadIdx.x;
    size_t base = row * Dc;
    float x0 = a[base + t]       + bsrc[base + t];
    float x1 = a[base + t + 256] + bsrc[base + t + 256];
    __shared__ float red[256];
    red[t] = x0 + x1;
    __syncthreads();
    for (int s = 128; s > 0; s >>= 1) { if (t < s) red[t] += red[t + s]; __syncthreads(); }
    float mu = red[0] * (1.0f / Dc);
    __syncthreads();
    float d0 = x0 - mu, d1 = x1 - mu;
    red[t] = d0 * d0 + d1 * d1;
    __syncthreads();
    for (int s = 128; s > 0; s >>= 1) { if (t < s) red[t] += red[t + s]; __syncthreads(); }
    float inv = rsqrtf(red[0] * (1.0f / Dc) + EPSc);
    out[base + t]       = d0 * inv * gamma[t]       + beta[t];
    out[base + t + 256] = d1 * inv * gamma[t + 256] + beta[t + 256];
}

// ---------------- host orchestration ----------------
static void launch_gemm(const float* A, const float* BT, const float* bias, float* C,
                        int M, int N, int K, bool relu) {
    dim3 grid(N / 128, M / 128);
    if (relu) gemm_mma<true ><<<grid, 256>>>(A, BT, bias, C, M, N, K);
    else      gemm_mma<false><<<grid, 256>>>(A, BT, bias, C, M, N, K);
}

static void run_mha(const float* xq, const float* xkv,
                    const unsigned char* mq, const unsigned char* mk, int causal,
                    const float* wT, const float* b,
                    float* qp, float* kp, float* vp, float* attnp, float* scoresp,
                    float* outp) {
    launch_gemm(xq,  wT + 0 * (size_t)Dc * Dc, b + 0 * Dc, qp, BSc, Dc, Dc, false);
    launch_gemm(xkv, wT + 1 * (size_t)Dc * Dc, b + 1 * Dc, kp, BSc, Dc, Dc, false);
    launch_gemm(xkv, wT + 2 * (size_t)Dc * Dc, b + 2 * Dc, vp, BSc, Dc, Dc, false);
    dim3 blk(256);
    dim3 gqk(Sc / 64, Sc / 64, Bc * NHc);
    qk_scores<<<gqk, blk>>>(qp, kp, mq, mk, scoresp, causal);
    softmax_rows<<<Bc * NHc * Sc, blk>>>(scoresp);
    dim3 gav(1, Sc / 64, Bc * NHc);
    av_kernel<<<gav, blk>>>(scoresp, vp, attnp);
    launch_gemm(attnp, wT + 3 * (size_t)Dc * Dc, b + 3 * Dc, outp, BSc, Dc, Dc, false);
}

extern "C" void kernel_launch(void* const* d_in, const int* in_sizes, int n_in,
                              void* d_out, int out_size) {
    const int*   inputs  = (const int*)d_in[0];
    const int*   outputs = (const int*)d_in[1];
    const float* emi = (const float*)d_in[2];
    const float* emo = (const float*)d_in[3];
    const float* enc_attn_w = (const float*)d_in[4];
    const float* enc_attn_b = (const float*)d_in[5];
    const float* enc_ln     = (const float*)d_in[6];
    const float* enc_ffn_w1 = (const float*)d_in[7];
    const float* enc_ffn_b1 = (const float*)d_in[8];
    const float* enc_ffn_w2 = (const float*)d_in[9];
    const float* enc_ffn_b2 = (const float*)d_in[10];
    const float* dec_self_w  = (const float*)d_in[11];
    const float* dec_self_b  = (const float*)d_in[12];
    const float* dec_cross_w = (const float*)d_in[13];
    const float* dec_cross_b = (const float*)d_in[14];
    const float* dec_ln      = (const float*)d_in[15];
    const float* dec_ffn_w1 = (const float*)d_in[16];
    const float* dec_ffn_b1 = (const float*)d_in[17];
    const float* dec_ffn_w2 = (const float*)d_in[18];
    const float* dec_ffn_b2 = (const float*)d_in[19];

    float *xp, *yp, *qp, *kp, *vp, *attnp, *tmpp, *hidp, *scoresp;
    float *wta_enc, *wta_self, *wta_cross, *wt_ef1, *wt_ef2, *wt_df1, *wt_df2;
    unsigned char *mxp, *myp;
    cudaGetSymbolAddress((void**)&xp, g_x);
    cudaGetSymbolAddress((void**)&yp, g_y);
    cudaGetSymbolAddress((void**)&qp, g_q);
    cudaGetSymbolAddress((void**)&kp, g_k);
    cudaGetSymbolAddress((void**)&vp, g_v);
    cudaGetSymbolAddress((void**)&attnp, g_attn);
    cudaGetSymbolAddress((void**)&tmpp, g_tmp);
    cudaGetSymbolAddress((void**)&hidp, g_hid);
    cudaGetSymbolAddress((void**)&scoresp, g_scores);
    cudaGetSymbolAddress((void**)&mxp, g_mx);
    cudaGetSymbolAddress((void**)&myp, g_my);
    cudaGetSymbolAddress((void**)&wta_enc,   g_wt_enc_attn);
    cudaGetSymbolAddress((void**)&wta_self,  g_wt_dec_self);
    cudaGetSymbolAddress((void**)&wta_cross, g_wt_dec_cross);
    cudaGetSymbolAddress((void**)&wt_ef1, g_wt_enc_f1);
    cudaGetSymbolAddress((void**)&wt_ef2, g_wt_enc_f2);
    cudaGetSymbolAddress((void**)&wt_df1, g_wt_dec_f1);
    cudaGetSymbolAddress((void**)&wt_df2, g_wt_dec_f2);

    // -------- weight transposes (tf32-rounded) --------
    dim3 tblk(32, 8);
    transpose_tf32<<<dim3(Dc / 32, Dc / 32, Lc * 4), tblk>>>(enc_attn_w,  wta_enc,   Dc, Dc);
    transpose_tf32<<<dim3(Dc / 32, Dc / 32, Lc * 4), tblk>>>(dec_self_w,  wta_self,  Dc, Dc);
    transpose_tf32<<<dim3(Dc / 32, Dc / 32, Lc * 4), tblk>>>(dec_cross_w, wta_cross, Dc, Dc);
    transpose_tf32<<<dim3(HIDc / 32, Dc / 32, Lc), tblk>>>(enc_ffn_w1, wt_ef1, Dc, HIDc);
    transpose_tf32<<<dim3(Dc / 32, HIDc / 32, Lc), tblk>>>(enc_ffn_w2, wt_ef2, HIDc, Dc);
    transpose_tf32<<<dim3(HIDc / 32, Dc / 32, Lc), tblk>>>(dec_ffn_w1, wt_df1, Dc, HIDc);
    transpose_tf32<<<dim3(Dc / 32, HIDc / 32, Lc), tblk>>>(dec_ffn_w2, wt_df2, HIDc, Dc);

    dim3 blk(256);
    embed_pe_kernel<<<BSc, blk>>>(inputs,  emi, xp, mxp);
    embed_pe_kernel<<<BSc, blk>>>(outputs, emo, yp, myp);

    // ---------------- encoder ----------------
    for (int l = 0; l < Lc; ++l) {
        const float* wT = wta_enc + (size_t)l * 4 * Dc * Dc;
        const float* ab = enc_attn_b + (size_t)l * 4 * Dc;
        run_mha(xp, xp, mxp, mxp, 0, wT, ab, qp, kp, vp, attnp, scoresp, tmpp);
        const float* ln0 = enc_ln + (((size_t)l * 2 + 0) * 2) * Dc;
        add_ln_kernel<<<BSc, blk>>>(xp, tmpp, ln0, ln0 + Dc, xp);
        launch_gemm(xp, wt_ef1 + (size_t)l * Dc * HIDc, enc_ffn_b1 + (size_t)l * HIDc,
                    hidp, BSc, HIDc, Dc, true);
        launch_gemm(hidp, wt_ef2 + (size_t)l * Dc * HIDc, enc_ffn_b2 + (size_t)l * Dc,
                    tmpp, BSc, Dc, HIDc, false);
        const float* ln1 = enc_ln + (((size_t)l * 2 + 1) * 2) * Dc;
        add_ln_kernel<<<BSc, blk>>>(xp, tmpp, ln1, ln1 + Dc, xp);
    }

    // ---------------- decoder ----------------
    float* fout = (float*)d_out;
    for (int l = 0; l < Lc; ++l) {
        const float* swT = wta_self + (size_t)l * 4 * Dc * Dc;
        const float* sb  = dec_self_b + (size_t)l * 4 * Dc;
        run_mha(yp, yp, myp, myp, 1, swT, sb, qp, kp, vp, attnp, scoresp, tmpp);
        const float* ln0 = dec_ln + (((size_t)l * 3 + 0) * 2) * Dc;
        add_ln_kernel<<<BSc, blk>>>(yp, tmpp, ln0, ln0 + Dc, yp);

        const float* cwT = wta_cross + (size_t)l * 4 * Dc * Dc;
        const float* cb  = dec_cross_b + (size_t)l * 4 * Dc;
        run_mha(yp, xp, myp, mxp, 0, cwT, cb, qp, kp, vp, attnp, scoresp, tmpp);
        const float* ln1 = dec_ln + (((size_t)l * 3 + 1) * 2) * Dc;
        add_ln_kernel<<<BSc, blk>>>(yp, tmpp, ln1, ln1 + Dc, yp);

        launch_gemm(yp, wt_df1 + (size_t)l * Dc * HIDc, dec_ffn_b1 + (size_t)l * HIDc,
                    hidp, BSc, HIDc, Dc, true);
        launch_gemm(hidp, wt_df2 + (size_t)l * Dc * HIDc, dec_ffn_b2 + (size_t)l * Dc,
                    tmpp, BSc, Dc, HIDc, false);
        const float* ln2 = dec_ln + (((size_t)l * 3 + 2) * 2) * Dc;
        float* dst = (l == Lc - 1) ? fout : yp;
        add_ln_kernel<<<BSc, blk>>>(yp, tmpp, ln2, ln2 + Dc, dst);
    }
    (void)in_sizes; (void)n_in; (void)out_size;
}

// round 4
// speedup vs baseline: 2.5742x; 1.4960x over previous
#include <cuda_runtime.h>
#include <math.h>
#include <cstdint>

// ---------------- problem constants ----------------
#define Bc   8
#define Sc   512
#define Dc   512
#define NHc  8
#define DHc  64
#define Lc   6
#define HIDc 2048
#define EPSc 1e-5f
#define BSc  (Bc * Sc)          // 4096 tokens
#define SCALEc 0.125f           // 1/sqrt(64)

// ---------------- device scratch ----------------
__device__ float g_x[BSc * Dc];
__device__ float g_y[BSc * Dc];
__device__ float g_q[BSc * Dc];
__device__ float g_k[BSc * Dc];
__device__ float g_v[BSc * Dc];
__device__ float g_attn[BSc * Dc];
__device__ float g_tmp[BSc * Dc];
__device__ float g_hid[BSc * HIDc];
__device__ unsigned char g_mx[BSc];
__device__ unsigned char g_my[BSc];
// transposed (tf32-rounded) weights: [N][K]
__device__ float g_wt_enc_attn[Lc * 4 * Dc * Dc];
__device__ float g_wt_dec_self[Lc * 4 * Dc * Dc];
__device__ float g_wt_dec_cross[Lc * 4 * Dc * Dc];
__device__ float g_wt_enc_f1[Lc * Dc * HIDc];
__device__ float g_wt_enc_f2[Lc * Dc * HIDc];
__device__ float g_wt_dec_f1[Lc * Dc * HIDc];
__device__ float g_wt_dec_f2[Lc * Dc * HIDc];

__device__ __forceinline__ float neg_inf_f() { return __int_as_float(0xff800000u); }

__device__ __forceinline__ uint32_t round_tf32(float v) {
    uint32_t u; asm("cvt.rna.tf32.f32 %0, %1;" : "=r"(u) : "f"(v)); return u;
}

// mma.sync m16n8k8 tf32 (sm_80+ family-compatible; NO tcgen05 on this toolchain)
__device__ __forceinline__ void mma_16n8k8(float c[4], const uint32_t a[4], const uint32_t b[2]) {
    asm volatile(
        "mma.sync.aligned.m16n8k8.row.col.f32.tf32.tf32.f32 "
        "{%0,%1,%2,%3}, {%4,%5,%6,%7}, {%8,%9}, {%0,%1,%2,%3};"
        : "+f"(c[0]), "+f"(c[1]), "+f"(c[2]), "+f"(c[3])
        : "r"(a[0]), "r"(a[1]), "r"(a[2]), "r"(a[3]), "r"(b[0]), "r"(b[1]));
}

// ---------------- weight transpose (with tf32 rounding) ----------------
__global__ void transpose_tf32(const float* __restrict__ in, float* __restrict__ out,
                               int R, int C) {
    __shared__ float tile[32][33];
    const float* src = in + (size_t)blockIdx.z * R * C;
    float* dst = out + (size_t)blockIdx.z * R * C;
    int c0 = blockIdx.x * 32, r0 = blockIdx.y * 32;
    int tx = threadIdx.x, ty = threadIdx.y;          // 32 x 8
    #pragma unroll
    for (int i = 0; i < 32; i += 8)
        tile[ty + i][tx] = src[(size_t)(r0 + ty + i) * C + c0 + tx];
    __syncthreads();
    #pragma unroll
    for (int i = 0; i < 32; i += 8) {
        float v = tile[tx][ty + i];
        dst[(size_t)(c0 + ty + i) * R + r0 + tx] = __uint_as_float(round_tf32(v));
    }
}

// ---------------- tf32 mma GEMM: C[M,N] = A[M,K] @ BT[N,K]^T + bias ----------------
#define PADK 36   // (row*36+k)%32 == (row*4+k)%32 -> conflict-free fragment loads

template<bool RELU>
__global__ void __launch_bounds__(256) gemm_mma(const float* __restrict__ A,
                                                const float* __restrict__ BT,
                                                const float* __restrict__ bias,
                                                float* __restrict__ C,
                                                int M, int N, int K) {
    __shared__ uint32_t As[128 * PADK];
    __shared__ uint32_t Bs[128 * PADK];
    int tid = threadIdx.x;
    int lane = tid & 31, wid = tid >> 5;
    int wm = wid & 1;
    int wn = wid >> 1;
    int row0 = blockIdx.y * 128, col0 = blockIdx.x * 128;
    int g = lane >> 2, tg = lane & 3;

    float acc[4][4][4];
    #pragma unroll
    for (int mi = 0; mi < 4; mi++)
        #pragma unroll
        for (int ni = 0; ni < 4; ni++)
            #pragma unroll
            for (int r = 0; r < 4; r++) acc[mi][ni][r] = 0.0f;

    for (int k0 = 0; k0 < K; k0 += 32) {
        #pragma unroll
        for (int i = 0; i < 4; ++i) {
            int idx = tid + i * 256;
            int r = idx >> 3, cc = (idx & 7) * 4;
            float4 va = *reinterpret_cast<const float4*>(&A[(size_t)(row0 + r) * K + k0 + cc]);
            uint4 ua = make_uint4(round_tf32(va.x), round_tf32(va.y),
                                  round_tf32(va.z), round_tf32(va.w));
            *reinterpret_cast<uint4*>(&As[r * PADK + cc]) = ua;
            float4 vb = *reinterpret_cast<const float4*>(&BT[(size_t)(col0 + r) * K + k0 + cc]);
            uint4 ub = make_uint4(round_tf32(vb.x), round_tf32(vb.y),
                                  round_tf32(vb.z), round_tf32(vb.w));
            *reinterpret_cast<uint4*>(&Bs[r * PADK + cc]) = ub;
        }
        __syncthreads();

        #pragma unroll
        for (int ki = 0; ki < 4; ++ki) {
            int ak = ki * 8 + tg;
            uint32_t afr[4][4];
            #pragma unroll
            for (int mi = 0; mi < 4; mi++) {
                int r = wm * 64 + mi * 16 + g;
                afr[mi][0] = As[(r)     * PADK + ak];
                afr[mi][1] = As[(r + 8) * PADK + ak];
                afr[mi][2] = As[(r)     * PADK + ak + 4];
                afr[mi][3] = As[(r + 8) * PADK + ak + 4];
            }
            uint32_t bfr[4][2];
            #pragma unroll
            for (int ni = 0; ni < 4; ni++) {
                int n = wn * 32 + ni * 8 + g;
                bfr[ni][0] = Bs[n * PADK + ak];
                bfr[ni][1] = Bs[n * PADK + ak + 4];
            }
            #pragma unroll
            for (int mi = 0; mi < 4; mi++)
                #pragma unroll
                for (int ni = 0; ni < 4; ni++)
                    mma_16n8k8(acc[mi][ni], afr[mi], bfr[ni]);
        }
        __syncthreads();
    }

    #pragma unroll
    for (int mi = 0; mi < 4; mi++) {
        int r0r = row0 + wm * 64 + mi * 16 + g;
        #pragma unroll
        for (int ni = 0; ni < 4; ni++) {
            int cb = col0 + wn * 32 + ni * 8 + tg * 2;
            float b0 = bias[cb], b1 = bias[cb + 1];
            float v0 = acc[mi][ni][0] + b0, v1 = acc[mi][ni][1] + b1;
            float v2 = acc[mi][ni][2] + b0, v3 = acc[mi][ni][3] + b1;
            if (RELU) { v0 = fmaxf(v0, 0.f); v1 = fmaxf(v1, 0.f);
                        v2 = fmaxf(v2, 0.f); v3 = fmaxf(v3, 0.f); }
            *reinterpret_cast<float2*>(&C[(size_t)(r0r)     * N + cb]) = make_float2(v0, v1);
            *reinterpret_cast<float2*>(&C[(size_t)(r0r + 8) * N + cb]) = make_float2(v2, v3);
        }
    }
}

// ---------------- fused flash attention (tf32 mma) ----------------
// grid (Sc/128, B*NH), 256 threads (8 warps x 16 q-rows). K-tile = 64 keys.
// smem: Qs[128][FPAD] + Ks[64][FPAD] + Vt[64][FPAD] + Ps[128][FPAD] + mks[64]
#define FPAD 68   // 68 % 32 == 4 -> same conflict-free property as PADK
#define FLASH_SMEM ((128 + 64 + 64 + 128) * FPAD * 4 + 64)

__global__ void __launch_bounds__(256) flash_attn(
    const float* __restrict__ q, const float* __restrict__ k, const float* __restrict__ v,
    const unsigned char* __restrict__ mqg, const unsigned char* __restrict__ mkg,
    float* __restrict__ o, int causal)
{
    extern __shared__ char sm[];
    uint32_t* Qs = reinterpret_cast<uint32_t*>(sm);
    uint32_t* Ks = Qs + 128 * FPAD;
    uint32_t* Vt = Ks + 64 * FPAD;
    uint32_t* Ps = Vt + 64 * FPAD;
    unsigned char* mks = reinterpret_cast<unsigned char*>(Ps + 128 * FPAD);

    int tid = threadIdx.x, lane = tid & 31, wid = tid >> 5;
    int bh = blockIdx.y, b = bh >> 3, h = bh & 7;
    int q0 = blockIdx.x * 128;
    const float* Qg = q + (size_t)b * Sc * Dc + h * DHc;
    const float* Kg = k + (size_t)b * Sc * Dc + h * DHc;
    const float* Vg = v + (size_t)b * Sc * Dc + h * DHc;
    int g = lane >> 2, tg = lane & 3;
    int rg = wid * 16 + g;                 // local q row (this thread also owns rg+8)
    int qi0 = q0 + rg, qi1 = qi0 + 8;

    // load Q tile [128 x 64], tf32-rounded
    #pragma unroll
    for (int i = 0; i < 8; ++i) {
        int idx = tid + i * 256;
        int r = idx >> 4, c = (idx & 15) * 4;
        float4 va = *reinterpret_cast<const float4*>(&Qg[(size_t)(q0 + r) * Dc + c]);
        Qs[r * FPAD + c + 0] = round_tf32(va.x);
        Qs[r * FPAD + c + 1] = round_tf32(va.y);
        Qs[r * FPAD + c + 2] = round_tf32(va.z);
        Qs[r * FPAD + c + 3] = round_tf32(va.w);
    }
    bool mrow0 = mqg[b * Sc + qi0] != 0;
    bool mrow1 = mqg[b * Sc + qi1] != 0;

    float m0 = -1e30f, m1 = -1e30f, l0 = 0.f, l1 = 0.f;
    float oacc[8][4];
    #pragma unroll
    for (int ni = 0; ni < 8; ni++) { oacc[ni][0] = oacc[ni][1] = oacc[ni][2] = oacc[ni][3] = 0.f; }

    int nkt = causal ? ((q0 >> 6) + 2) : (Sc / 64);
    for (int kt = 0; kt < nkt; ++kt) {
        int k0 = kt * 64;
        __syncthreads();                    // previous tile fully consumed (also covers Q on kt=0)
        #pragma unroll
        for (int i = 0; i < 4; ++i) {
            int idx = tid + i * 256;
            int r = idx >> 4, c = (idx & 15) * 4;
            float4 vk = *reinterpret_cast<const float4*>(&Kg[(size_t)(k0 + r) * Dc + c]);
            Ks[r * FPAD + c + 0] = round_tf32(vk.x);
            Ks[r * FPAD + c + 1] = round_tf32(vk.y);
            Ks[r * FPAD + c + 2] = round_tf32(vk.z);
            Ks[r * FPAD + c + 3] = round_tf32(vk.w);
            float4 vv = *reinterpret_cast<const float4*>(&Vg[(size_t)(k0 + r) * Dc + c]);
            Vt[(c + 0) * FPAD + r] = round_tf32(vv.x);   // transposed: Vt[dh][key]
            Vt[(c + 1) * FPAD + r] = round_tf32(vv.y);
            Vt[(c + 2) * FPAD + r] = round_tf32(vv.z);
            Vt[(c + 3) * FPAD + r] = round_tf32(vv.w);
        }
        if (tid < 64) mks[tid] = mkg[b * Sc + k0 + tid];
        __syncthreads();

        // ---- S = Q @ K^T  (warp tile 16 x 64) ----
        float s[8][4];
        #pragma unroll
        for (int ni = 0; ni < 8; ni++) { s[ni][0] = s[ni][1] = s[ni][2] = s[ni][3] = 0.f; }
        #pragma unroll
        for (int ki = 0; ki < 8; ++ki) {
            int ak = ki * 8 + tg;
            uint32_t a[4] = { Qs[rg * FPAD + ak],       Qs[(rg + 8) * FPAD + ak],
                              Qs[rg * FPAD + ak + 4],   Qs[(rg + 8) * FPAD + ak + 4] };
            #pragma unroll
            for (int ni = 0; ni < 8; ni++) {
                uint32_t bfr[2] = { Ks[(ni * 8 + g) * FPAD + ak],
                                    Ks[(ni * 8 + g) * FPAD + ak + 4] };
                mma_16n8k8(s[ni], a, bfr);
            }
        }

        // ---- scale + mask ----
        float rmax0 = neg_inf_f(), rmax1 = neg_inf_f();
        #pragma unroll
        for (int ni = 0; ni < 8; ni++) {
            int cloc = ni * 8 + 2 * tg;
            int cg = k0 + cloc;
            bool mkA = mks[cloc] != 0, mkB = mks[cloc + 1] != 0;
            float v0 = (mrow0 || mkA || (causal && cg     > qi0)) ? neg_inf_f() : s[ni][0] * SCALEc;
            float v1 = (mrow0 || mkB || (causal && cg + 1 > qi0)) ? neg_inf_f() : s[ni][1] * SCALEc;
            float v2 = (mrow1 || mkA || (causal && cg     > qi1)) ? neg_inf_f() : s[ni][2] * SCALEc;
            float v3 = (mrow1 || mkB || (causal && cg + 1 > qi1)) ? neg_inf_f() : s[ni][3] * SCALEc;
            s[ni][0] = v0; s[ni][1] = v1; s[ni][2] = v2; s[ni][3] = v3;
            rmax0 = fmaxf(rmax0, fmaxf(v0, v1));
            rmax1 = fmaxf(rmax1, fmaxf(v2, v3));
        }
        rmax0 = fmaxf(rmax0, __shfl_xor_sync(0xffffffffu, rmax0, 1));
        rmax0 = fmaxf(rmax0, __shfl_xor_sync(0xffffffffu, rmax0, 2));
        rmax1 = fmaxf(rmax1, __shfl_xor_sync(0xffffffffu, rmax1, 1));
        rmax1 = fmaxf(rmax1, __shfl_xor_sync(0xffffffffu, rmax1, 2));

        float mn0 = fmaxf(m0, rmax0), mn1 = fmaxf(m1, rmax1);
        float sc0 = __expf(m0 - mn0), sc1 = __expf(m1 - mn1);
        float rs0 = 0.f, rs1 = 0.f;
        #pragma unroll
        for (int ni = 0; ni < 8; ni++) {
            int cloc = ni * 8 + 2 * tg;
            float p0 = __expf(s[ni][0] - mn0), p1 = __expf(s[ni][1] - mn0);
            float p2 = __expf(s[ni][2] - mn1), p3 = __expf(s[ni][3] - mn1);
            rs0 += p0 + p1; rs1 += p2 + p3;
            Ps[rg * FPAD + cloc]           = round_tf32(p0);
            Ps[rg * FPAD + cloc + 1]       = round_tf32(p1);
            Ps[(rg + 8) * FPAD + cloc]     = round_tf32(p2);
            Ps[(rg + 8) * FPAD + cloc + 1] = round_tf32(p3);
        }
        rs0 += __shfl_xor_sync(0xffffffffu, rs0, 1);
        rs0 += __shfl_xor_sync(0xffffffffu, rs0, 2);
        rs1 += __shfl_xor_sync(0xffffffffu, rs1, 1);
        rs1 += __shfl_xor_sync(0xffffffffu, rs1, 2);
        l0 = l0 * sc0 + rs0; l1 = l1 * sc1 + rs1;
        m0 = mn0; m1 = mn1;
        #pragma unroll
        for (int ni = 0; ni < 8; ni++) {
            oacc[ni][0] *= sc0; oacc[ni][1] *= sc0;
            oacc[ni][2] *= sc1; oacc[ni][3] *= sc1;
        }
        __syncwarp();    // Ps rows are warp-exclusive; order stores vs cross-lane loads

        // ---- O += P @ V  (A = Ps rows, B = Vt[dh][key]) ----
        #pragma unroll
        for (int ki = 0; ki < 8; ++ki) {
            int ak = ki * 8 + tg;
            uint32_t a[4] = { Ps[rg * FPAD + ak],       Ps[(rg + 8) * FPAD + ak],
                              Ps[rg * FPAD + ak + 4],   Ps[(rg + 8) * FPAD + ak + 4] };
            #pragma unroll
            for (int ni = 0; ni < 8; ni++) {
                uint32_t bfr[2] = { Vt[(ni * 8 + g) * FPAD + ak],
                                    Vt[(ni * 8 + g) * FPAD + ak + 4] };
                mma_16n8k8(oacc[ni], a, bfr);
            }
        }
    }

    float inv0 = (l0 > 0.f) ? 1.f / l0 : 0.f;
    float inv1 = (l1 > 0.f) ? 1.f / l1 : 0.f;
    size_t ob0 = ((size_t)b * Sc + qi0) * Dc + h * DHc;
    size_t ob1 = ((size_t)b * Sc + qi1) * Dc + h * DHc;
    #pragma unroll
    for (int ni = 0; ni < 8; ni++) {
        int cc = ni * 8 + 2 * tg;
        *reinterpret_cast<float2*>(&o[ob0 + cc]) = make_float2(oacc[ni][0] * inv0, oacc[ni][1] * inv0);
        *reinterpret_cast<float2*>(&o[ob1 + cc]) = make_float2(oacc[ni][2] * inv1, oacc[ni][3] * inv1);
    }
}

// ---------------- embedding + positional encoding (+ pad mask) ----------------
__global__ void embed_pe_kernel(const int* __restrict__ toks,
                                const float* __restrict__ emb,
                                float* __restrict__ out,
                                unsigned char* __restrict__ mask) {
    int pos = blockIdx.x % Sc;
    int b   = blockIdx.x / Sc;
    int tok = toks[b * Sc + pos];
    int t = threadIdx.x;
    if (t == 0) mask[b * Sc + pos] = (tok == 0) ? 1 : 0;
    const float c = -logf(10000.0f) / (float)Dc;
    size_t base = ((size_t)b * Sc + pos) * Dc;
    #pragma unroll
    for (int d = t; d < Dc; d += 256) {
        int i = d >> 1;
        float freq = __expf((float)(2 * i) * c);
        float ang  = (float)pos * freq;
        float pe   = (d & 1) ? cosf(ang) : sinf(ang);
        out[base + d] = emb[(size_t)tok * Dc + d] + pe;
    }
}

// ---------------- out = LayerNorm(a + b) * gamma + beta ----------------
__global__ void add_ln_kernel(const float* __restrict__ a, const float* __restrict__ bsrc,
                              const float* __restrict__ gamma, const float* __restrict__ beta,
                              float* __restrict__ out) {
    size_t row = blockIdx.x;
    int t = threadIdx.x;
    size_t base = row * Dc;
    float x0 = a[base + t]       + bsrc[base + t];
    float x1 = a[base + t + 256] + bsrc[base + t + 256];
    __shared__ float red[256];
    red[t] = x0 + x1;
    __syncthreads();
    for (int s = 128; s > 0; s >>= 1) { if (t < s) red[t] += red[t + s]; __syncthreads(); }
    float mu = red[0] * (1.0f / Dc);
    __syncthreads();
    float d0 = x0 - mu, d1 = x1 - mu;
    red[t] = d0 * d0 + d1 * d1;
    __syncthreads();
    for (int s = 128; s > 0; s >>= 1) { if (t < s) red[t] += red[t + s]; __syncthreads(); }
    float inv = rsqrtf(red[0] * (1.0f / Dc) + EPSc);
    out[base + t]       = d0 * inv * gamma[t]       + beta[t];
    out[base + t + 256] = d1 * inv * gamma[t + 256] + beta[t + 256];
}

// ---------------- host orchestration ----------------
static void launch_gemm(const float* A, const float* BT, const float* bias, float* C,
                        int M, int N, int K, bool relu) {
    dim3 grid(N / 128, M / 128);
    if (relu) gemm_mma<true ><<<grid, 256>>>(A, BT, bias, C, M, N, K);
    else      gemm_mma<false><<<grid, 256>>>(A, BT, bias, C, M, N, K);
}

static void run_mha(const float* xq, const float* xkv,
                    const unsigned char* mq, const unsigned char* mk, int causal,
                    const float* wT, const float* b,
                    float* qp, float* kp, float* vp, float* attnp, float* outp) {
    launch_gemm(xq,  wT + 0 * (size_t)Dc * Dc, b + 0 * Dc, qp, BSc, Dc, Dc, false);
    launch_gemm(xkv, wT + 1 * (size_t)Dc * Dc, b + 1 * Dc, kp, BSc, Dc, Dc, false);
    launch_gemm(xkv, wT + 2 * (size_t)Dc * Dc, b + 2 * Dc, vp, BSc, Dc, Dc, false);
    dim3 gfl(Sc / 128, Bc * NHc);
    flash_attn<<<gfl, 256, FLASH_SMEM>>>(qp, kp, vp, mq, mk, attnp, causal);
    launch_gemm(attnp, wT + 3 * (size_t)Dc * Dc, b + 3 * Dc, outp, BSc, Dc, Dc, false);
}

extern "C" void kernel_launch(void* const* d_in, const int* in_sizes, int n_in,
                              void* d_out, int out_size) {
    const int*   inputs  = (const int*)d_in[0];
    const int*   outputs = (const int*)d_in[1];
    const float* emi = (const float*)d_in[2];
    const float* emo = (const float*)d_in[3];
    const float* enc_attn_w = (const float*)d_in[4];
    const float* enc_attn_b = (const float*)d_in[5];
    const float* enc_ln     = (const float*)d_in[6];
    const float* enc_ffn_w1 = (const float*)d_in[7];
    const float* enc_ffn_b1 = (const float*)d_in[8];
    const float* enc_ffn_w2 = (const float*)d_in[9];
    const float* enc_ffn_b2 = (const float*)d_in[10];
    const float* dec_self_w  = (const float*)d_in[11];
    const float* dec_self_b  = (const float*)d_in[12];
    const float* dec_cross_w = (const float*)d_in[13];
    const float* dec_cross_b = (const float*)d_in[14];
    const float* dec_ln      = (const float*)d_in[15];
    const float* dec_ffn_w1 = (const float*)d_in[16];
    const float* dec_ffn_b1 = (const float*)d_in[17];
    const float* dec_ffn_w2 = (const float*)d_in[18];
    const float* dec_ffn_b2 = (const float*)d_in[19];

    float *xp, *yp, *qp, *kp, *vp, *attnp, *tmpp, *hidp;
    float *wta_enc, *wta_self, *wta_cross, *wt_ef1, *wt_ef2, *wt_df1, *wt_df2;
    unsigned char *mxp, *myp;
    cudaGetSymbolAddress((void**)&xp, g_x);
    cudaGetSymbolAddress((void**)&yp, g_y);
    cudaGetSymbolAddress((void**)&qp, g_q);
    cudaGetSymbolAddress((void**)&kp, g_k);
    cudaGetSymbolAddress((void**)&vp, g_v);
    cudaGetSymbolAddress((void**)&attnp, g_attn);
    cudaGetSymbolAddress((void**)&tmpp, g_tmp);
    cudaGetSymbolAddress((void**)&hidp, g_hid);
    cudaGetSymbolAddress((void**)&mxp, g_mx);
    cudaGetSymbolAddress((void**)&myp, g_my);
    cudaGetSymbolAddress((void**)&wta_enc,   g_wt_enc_attn);
    cudaGetSymbolAddress((void**)&wta_self,  g_wt_dec_self);
    cudaGetSymbolAddress((void**)&wta_cross, g_wt_dec_cross);
    cudaGetSymbolAddress((void**)&wt_ef1, g_wt_enc_f1);
    cudaGetSymbolAddress((void**)&wt_ef2, g_wt_enc_f2);
    cudaGetSymbolAddress((void**)&wt_df1, g_wt_dec_f1);
    cudaGetSymbolAddress((void**)&wt_df2, g_wt_dec_f2);

    cudaFuncSetAttribute(flash_attn, cudaFuncAttributeMaxDynamicSharedMemorySize, FLASH_SMEM);

    // -------- weight transposes (tf32-rounded) --------
    dim3 tblk(32, 8);
    transpose_tf32<<<dim3(Dc / 32, Dc / 32, Lc * 4), tblk>>>(enc_attn_w,  wta_enc,   Dc, Dc);
    transpose_tf32<<<dim3(Dc / 32, Dc / 32, Lc * 4), tblk>>>(dec_self_w,  wta_self,  Dc, Dc);
    transpose_tf32<<<dim3(Dc / 32, Dc / 32, Lc * 4), tblk>>>(dec_cross_w, wta_cross, Dc, Dc);
    transpose_tf32<<<dim3(HIDc / 32, Dc / 32, Lc), tblk>>>(enc_ffn_w1, wt_ef1, Dc, HIDc);
    transpose_tf32<<<dim3(Dc / 32, HIDc / 32, Lc), tblk>>>(enc_ffn_w2, wt_ef2, HIDc, Dc);
    transpose_tf32<<<dim3(HIDc / 32, Dc / 32, Lc), tblk>>>(dec_ffn_w1, wt_df1, Dc, HIDc);
    transpose_tf32<<<dim3(Dc / 32, HIDc / 32, Lc), tblk>>>(dec_ffn_w2, wt_df2, HIDc, Dc);

    dim3 blk(256);
    embed_pe_kernel<<<BSc, blk>>>(inputs,  emi, xp, mxp);
    embed_pe_kernel<<<BSc, blk>>>(outputs, emo, yp, myp);

    // ---------------- encoder ----------------
    for (int l = 0; l < Lc; ++l) {
        const float* wT = wta_enc + (size_t)l * 4 * Dc * Dc;
        const float* ab = enc_attn_b + (size_t)l * 4 * Dc;
        run_mha(xp, xp, mxp, mxp, 0, wT, ab, qp, kp, vp, attnp, tmpp);
        const float* ln0 = enc_ln + (((size_t)l * 2 + 0) * 2) * Dc;
        add_ln_kernel<<<BSc, blk>>>(xp, tmpp, ln0, ln0 + Dc, xp);
        launch_gemm(xp, wt_ef1 + (size_t)l * Dc * HIDc, enc_ffn_b1 + (size_t)l * HIDc,
                    hidp, BSc, HIDc, Dc, true);
        launch_gemm(hidp, wt_ef2 + (size_t)l * Dc * HIDc, enc_ffn_b2 + (size_t)l * Dc,
                    tmpp, BSc, Dc, HIDc, false);
        const float* ln1 = enc_ln + (((size_t)l * 2 + 1) * 2) * Dc;
        add_ln_kernel<<<BSc, blk>>>(xp, tmpp, ln1, ln1 + Dc, xp);
    }

    // ---------------- decoder ----------------
    float* fout = (float*)d_out;
    for (int l = 0; l < Lc; ++l) {
        const float* swT = wta_self + (size_t)l * 4 * Dc * Dc;
        const float* sb  = dec_self_b + (size_t)l * 4 * Dc;
        run_mha(yp, yp, myp, myp, 1, swT, sb, qp, kp, vp, attnp, tmpp);
        const float* ln0 = dec_ln + (((size_t)l * 3 + 0) * 2) * Dc;
        add_ln_kernel<<<BSc, blk>>>(yp, tmpp, ln0, ln0 + Dc, yp);

        const float* cwT = wta_cross + (size_t)l * 4 * Dc * Dc;
        const float* cb  = dec_cross_b + (size_t)l * 4 * Dc;
        run_mha(yp, xp, myp, mxp, 0, cwT, cb, qp, kp, vp, attnp, tmpp);
        const float* ln1 = dec_ln + (((size_t)l * 3 + 1) * 2) * Dc;
        add_ln_kernel<<<BSc, blk>>>(yp, tmpp, ln1, ln1 + Dc, yp);

        launch_gemm(yp, wt_df1 + (size_t)l * Dc * HIDc, dec_ffn_b1 + (size_t)l * HIDc,
                    hidp, BSc, HIDc, Dc, true);
        launch_gemm(hidp, wt_df2 + (size_t)l * Dc * HIDc, dec_ffn_b2 + (size_t)l * Dc,
                    tmpp, BSc, Dc, HIDc, false);
        const float* ln2 = dec_ln + (((size_t)l * 3 + 2) * 2) * Dc;
        float* dst = (l == Lc - 1) ? fout : yp;
        add_ln_kernel<<<BSc, blk>>>(yp, tmpp, ln2, ln2 + Dc, dst);
    }
    (void)in_sizes; (void)n_in; (void)out_size;
}

// round 5
// speedup vs baseline: 3.6232x; 1.4075x over previous
#include <cuda_runtime.h>
#include <math.h>
#include <cstdint>

// ---------------- problem constants ----------------
#define Bc   8
#define Sc   512
#define Dc   512
#define NHc  8
#define DHc  64
#define Lc   6
#define HIDc 2048
#define EPSc 1e-5f
#define BSc  (Bc * Sc)          // 4096 tokens
#define SCALEc 0.125f           // 1/sqrt(64)

// ---------------- device scratch ----------------
__device__ float g_x[BSc * Dc];
__device__ float g_y[BSc * Dc];
__device__ float g_q[BSc * Dc];
__device__ float g_attn[BSc * Dc];
__device__ float g_tmp[BSc * Dc];
__device__ float g_hid[BSc * HIDc];      // FFN hidden / fused QKV / fused KV scratch
__device__ unsigned char g_mx[BSc];
__device__ unsigned char g_my[BSc];
// transposed (tf32-rounded) weights: [N][K]
__device__ float g_wt_enc_attn[Lc * 4 * Dc * Dc];
__device__ float g_wt_dec_self[Lc * 4 * Dc * Dc];
__device__ float g_wt_dec_cross[Lc * 4 * Dc * Dc];
__device__ float g_wt_enc_f1[Lc * Dc * HIDc];
__device__ float g_wt_enc_f2[Lc * Dc * HIDc];
__device__ float g_wt_dec_f1[Lc * Dc * HIDc];
__device__ float g_wt_dec_f2[Lc * Dc * HIDc];

__device__ __forceinline__ float neg_inf_f() { return __int_as_float(0xff800000u); }

__device__ __forceinline__ uint32_t round_tf32(float v) {
    uint32_t u; asm("cvt.rna.tf32.f32 %0, %1;" : "=r"(u) : "f"(v)); return u;
}
__device__ __forceinline__ uint32_t smem_u32(const void* p) {
    uint32_t a;
    asm("{ .reg .u64 t; cvta.to.shared.u64 t, %1; cvt.u32.u64 %0, t; }" : "=r"(a) : "l"(p));
    return a;
}

// mma.sync m16n8k8 tf32 (sm_80+ family-compatible; NO tcgen05 on this toolchain)
__device__ __forceinline__ void mma_16n8k8(float c[4], const uint32_t a[4], const uint32_t b[2]) {
    asm volatile(
        "mma.sync.aligned.m16n8k8.row.col.f32.tf32.tf32.f32 "
        "{%0,%1,%2,%3}, {%4,%5,%6,%7}, {%8,%9}, {%0,%1,%2,%3};"
        : "+f"(c[0]), "+f"(c[1]), "+f"(c[2]), "+f"(c[3])
        : "r"(a[0]), "r"(a[1]), "r"(a[2]), "r"(a[3]), "r"(b[0]), "r"(b[1]));
}

// ---------------- weight transpose (with tf32 rounding) ----------------
__global__ void transpose_tf32(const float* __restrict__ in, float* __restrict__ out,
                               int R, int C) {
    __shared__ float tile[32][33];
    const float* src = in + (size_t)blockIdx.z * R * C;
    float* dst = out + (size_t)blockIdx.z * R * C;
    int c0 = blockIdx.x * 32, r0 = blockIdx.y * 32;
    int tx = threadIdx.x, ty = threadIdx.y;          // 32 x 8
    #pragma unroll
    for (int i = 0; i < 32; i += 8)
        tile[ty + i][tx] = src[(size_t)(r0 + ty + i) * C + c0 + tx];
    __syncthreads();
    #pragma unroll
    for (int i = 0; i < 32; i += 8) {
        float v = tile[tx][ty + i];
        dst[(size_t)(c0 + ty + i) * R + r0 + tx] = __uint_as_float(round_tf32(v));
    }
}

// ---------------- tf32 mma GEMM, cp.async double-buffered ----------------
// C[M,N] = A[M,K] @ BT[N,K]^T + bias. 128x128 CTA tile, 8 warps, K-chunk 32.
#define PADK 36                         // (row*36+k)%32 == (row*4+k)%32 -> conflict-free
#define GBUF (128 * PADK)               // uint32s per operand tile
#define GEMM_SMEM (4 * GBUF * 4)        // 2 buffers x (A + B) x 4B = 73728 bytes

template<bool RELU>
__global__ void __launch_bounds__(256) gemm_mma(const float* __restrict__ A,
                                                const float* __restrict__ BT,
                                                const float* __restrict__ bias,
                                                float* __restrict__ C,
                                                int M, int N, int K) {
    extern __shared__ uint32_t gs[];
    uint32_t sbase = smem_u32(gs);
    int tid = threadIdx.x;
    int lane = tid & 31, wid = tid >> 5;
    int wm = wid & 1;
    int wn = wid >> 1;
    int row0 = blockIdx.y * 128, col0 = blockIdx.x * 128;
    int g = lane >> 2, tg = lane & 3;

    // per-thread load geometry (same for A and B tiles)
    int lr = tid >> 3, lc = (tid & 7) * 4;           // +i*32 rows per iteration

    float acc[4][4][4];
    #pragma unroll
    for (int mi = 0; mi < 4; mi++)
        #pragma unroll
        for (int ni = 0; ni < 4; ni++)
            #pragma unroll
            for (int r = 0; r < 4; r++) acc[mi][ni][r] = 0.0f;

    int nch = K >> 5;

    // prefetch chunk 0 into buffer 0
    {
        uint32_t abase = sbase;
        uint32_t bbase = sbase + GBUF * 4;
        #pragma unroll
        for (int i = 0; i < 4; ++i) {
            int r = lr + i * 32;
            uint32_t off = (uint32_t)(r * PADK + lc) * 4;
            const float* pa = &A[(size_t)(row0 + r) * K + lc];
            asm volatile("cp.async.cg.shared.global [%0], [%1], 16;" :: "r"(abase + off), "l"(pa));
            const float* pb = &BT[(size_t)(col0 + r) * K + lc];
            asm volatile("cp.async.cg.shared.global [%0], [%1], 16;" :: "r"(bbase + off), "l"(pb));
        }
        asm volatile("cp.async.commit_group;" ::: "memory");
    }

    for (int c = 0; c < nch; ++c) {
        int buf = c & 1;
        if (c + 1 < nch) {
            int k0 = (c + 1) << 5;
            uint32_t abase = sbase + (uint32_t)((buf ^ 1) * 2 * GBUF) * 4;
            uint32_t bbase = abase + GBUF * 4;
            #pragma unroll
            for (int i = 0; i < 4; ++i) {
                int r = lr + i * 32;
                uint32_t off = (uint32_t)(r * PADK + lc) * 4;
                const float* pa = &A[(size_t)(row0 + r) * K + k0 + lc];
                asm volatile("cp.async.cg.shared.global [%0], [%1], 16;" :: "r"(abase + off), "l"(pa));
                const float* pb = &BT[(size_t)(col0 + r) * K + k0 + lc];
                asm volatile("cp.async.cg.shared.global [%0], [%1], 16;" :: "r"(bbase + off), "l"(pb));
            }
            asm volatile("cp.async.commit_group;" ::: "memory");
            asm volatile("cp.async.wait_group 1;" ::: "memory");
        } else {
            asm volatile("cp.async.wait_group 0;" ::: "memory");
        }
        __syncthreads();

        const uint32_t* As = gs + buf * 2 * GBUF;
        const uint32_t* Bs = As + GBUF;

        #pragma unroll
        for (int ki = 0; ki < 4; ++ki) {
            int ak = ki * 8 + tg;
            uint32_t afr[4][4];
            #pragma unroll
            for (int mi = 0; mi < 4; mi++) {
                int r = wm * 64 + mi * 16 + g;
                // activations streamed raw fp32 -> RNA-round here (same numerics as before)
                afr[mi][0] = round_tf32(__uint_as_float(As[(r)     * PADK + ak]));
                afr[mi][1] = round_tf32(__uint_as_float(As[(r + 8) * PADK + ak]));
                afr[mi][2] = round_tf32(__uint_as_float(As[(r)     * PADK + ak + 4]));
                afr[mi][3] = round_tf32(__uint_as_float(As[(r + 8) * PADK + ak + 4]));
            }
            uint32_t bfr[4][2];
            #pragma unroll
            for (int ni = 0; ni < 4; ni++) {
                int n = wn * 32 + ni * 8 + g;
                bfr[ni][0] = Bs[n * PADK + ak];     // weights pre-rounded tf32
                bfr[ni][1] = Bs[n * PADK + ak + 4];
            }
            #pragma unroll
            for (int mi = 0; mi < 4; mi++)
                #pragma unroll
                for (int ni = 0; ni < 4; ni++)
                    mma_16n8k8(acc[mi][ni], afr[mi], bfr[ni]);
        }
        __syncthreads();   // buf fully consumed before it is overwritten two chunks later
    }

    #pragma unroll
    for (int mi = 0; mi < 4; mi++) {
        int r0r = row0 + wm * 64 + mi * 16 + g;
        #pragma unroll
        for (int ni = 0; ni < 4; ni++) {
            int cb = col0 + wn * 32 + ni * 8 + tg * 2;
            float b0 = bias[cb], b1 = bias[cb + 1];
            float v0 = acc[mi][ni][0] + b0, v1 = acc[mi][ni][1] + b1;
            float v2 = acc[mi][ni][2] + b0, v3 = acc[mi][ni][3] + b1;
            if (RELU) { v0 = fmaxf(v0, 0.f); v1 = fmaxf(v1, 0.f);
                        v2 = fmaxf(v2, 0.f); v3 = fmaxf(v3, 0.f); }
            *reinterpret_cast<float2*>(&C[(size_t)(r0r)     * N + cb]) = make_float2(v0, v1);
            *reinterpret_cast<float2*>(&C[(size_t)(r0r + 8) * N + cb]) = make_float2(v2, v3);
        }
    }
}

// ---------------- fused flash attention (tf32 mma), strided q/k/v ----------------
#define FPAD 68
#define FLASH_SMEM ((128 + 64 + 64 + 128) * FPAD * 4 + 64)

__global__ void __launch_bounds__(256) flash_attn(
    const float* __restrict__ q, int ldq,
    const float* __restrict__ k, const float* __restrict__ v, int ldkv,
    const unsigned char* __restrict__ mqg, const unsigned char* __restrict__ mkg,
    float* __restrict__ o, int causal)
{
    extern __shared__ char sm[];
    uint32_t* Qs = reinterpret_cast<uint32_t*>(sm);
    uint32_t* Ks = Qs + 128 * FPAD;
    uint32_t* Vt = Ks + 64 * FPAD;
    uint32_t* Ps = Vt + 64 * FPAD;
    unsigned char* mks = reinterpret_cast<unsigned char*>(Ps + 128 * FPAD);

    int tid = threadIdx.x, lane = tid & 31, wid = tid >> 5;
    int bh = blockIdx.y, b = bh >> 3, h = bh & 7;
    int q0 = blockIdx.x * 128;
    const float* Qg = q + (size_t)b * Sc * ldq + h * DHc;
    const float* Kg = k + (size_t)b * Sc * ldkv + h * DHc;
    const float* Vg = v + (size_t)b * Sc * ldkv + h * DHc;
    int g = lane >> 2, tg = lane & 3;
    int rg = wid * 16 + g;
    int qi0 = q0 + rg, qi1 = qi0 + 8;

    #pragma unroll
    for (int i = 0; i < 8; ++i) {
        int idx = tid + i * 256;
        int r = idx >> 4, c = (idx & 15) * 4;
        float4 va = *reinterpret_cast<const float4*>(&Qg[(size_t)(q0 + r) * ldq + c]);
        Qs[r * FPAD + c + 0] = round_tf32(va.x);
        Qs[r * FPAD + c + 1] = round_tf32(va.y);
        Qs[r * FPAD + c + 2] = round_tf32(va.z);
        Qs[r * FPAD + c + 3] = round_tf32(va.w);
    }
    bool mrow0 = mqg[b * Sc + qi0] != 0;
    bool mrow1 = mqg[b * Sc + qi1] != 0;

    float m0 = -1e30f, m1 = -1e30f, l0 = 0.f, l1 = 0.f;
    float oacc[8][4];
    #pragma unroll
    for (int ni = 0; ni < 8; ni++) { oacc[ni][0] = oacc[ni][1] = oacc[ni][2] = oacc[ni][3] = 0.f; }

    int nkt = causal ? ((q0 >> 6) + 2) : (Sc / 64);
    for (int kt = 0; kt < nkt; ++kt) {
        int k0 = kt * 64;
        __syncthreads();
        #pragma unroll
        for (int i = 0; i < 4; ++i) {
            int idx = tid + i * 256;
            int r = idx >> 4, c = (idx & 15) * 4;
            float4 vk = *reinterpret_cast<const float4*>(&Kg[(size_t)(k0 + r) * ldkv + c]);
            Ks[r * FPAD + c + 0] = round_tf32(vk.x);
            Ks[r * FPAD + c + 1] = round_tf32(vk.y);
            Ks[r * FPAD + c + 2] = round_tf32(vk.z);
            Ks[r * FPAD + c + 3] = round_tf32(vk.w);
            float4 vv = *reinterpret_cast<const float4*>(&Vg[(size_t)(k0 + r) * ldkv + c]);
            Vt[(c + 0) * FPAD + r] = round_tf32(vv.x);
            Vt[(c + 1) * FPAD + r] = round_tf32(vv.y);
            Vt[(c + 2) * FPAD + r] = round_tf32(vv.z);
            Vt[(c + 3) * FPAD + r] = round_tf32(vv.w);
        }
        if (tid < 64) mks[tid] = mkg[b * Sc + k0 + tid];
        __syncthreads();

        float s[8][4];
        #pragma unroll
        for (int ni = 0; ni < 8; ni++) { s[ni][0] = s[ni][1] = s[ni][2] = s[ni][3] = 0.f; }
        #pragma unroll
        for (int ki = 0; ki < 8; ++ki) {
            int ak = ki * 8 + tg;
            uint32_t a[4] = { Qs[rg * FPAD + ak],       Qs[(rg + 8) * FPAD + ak],
                              Qs[rg * FPAD + ak + 4],   Qs[(rg + 8) * FPAD + ak + 4] };
            #pragma unroll
            for (int ni = 0; ni < 8; ni++) {
                uint32_t bfr[2] = { Ks[(ni * 8 + g) * FPAD + ak],
                                    Ks[(ni * 8 + g) * FPAD + ak + 4] };
                mma_16n8k8(s[ni], a, bfr);
            }
        }

        float rmax0 = neg_inf_f(), rmax1 = neg_inf_f();
        #pragma unroll
        for (int ni = 0; ni < 8; ni++) {
            int cloc = ni * 8 + 2 * tg;
            int cg = k0 + cloc;
            bool mkA = mks[cloc] != 0, mkB = mks[cloc + 1] != 0;
            float v0 = (mrow0 || mkA || (causal && cg     > qi0)) ? neg_inf_f() : s[ni][0] * SCALEc;
            float v1 = (mrow0 || mkB || (causal && cg + 1 > qi0)) ? neg_inf_f() : s[ni][1] * SCALEc;
            float v2 = (mrow1 || mkA || (causal && cg     > qi1)) ? neg_inf_f() : s[ni][2] * SCALEc;
            float v3 = (mrow1 || mkB || (causal && cg + 1 > qi1)) ? neg_inf_f() : s[ni][3] * SCALEc;
            s[ni][0] = v0; s[ni][1] = v1; s[ni][2] = v2; s[ni][3] = v3;
            rmax0 = fmaxf(rmax0, fmaxf(v0, v1));
            rmax1 = fmaxf(rmax1, fmaxf(v2, v3));
        }
        rmax0 = fmaxf(rmax0, __shfl_xor_sync(0xffffffffu, rmax0, 1));
        rmax0 = fmaxf(rmax0, __shfl_xor_sync(0xffffffffu, rmax0, 2));
        rmax1 = fmaxf(rmax1, __shfl_xor_sync(0xffffffffu, rmax1, 1));
        rmax1 = fmaxf(rmax1, __shfl_xor_sync(0xffffffffu, rmax1, 2));

        float mn0 = fmaxf(m0, rmax0), mn1 = fmaxf(m1, rmax1);
        float sc0 = __expf(m0 - mn0), sc1 = __expf(m1 - mn1);
        float rs0 = 0.f, rs1 = 0.f;
        #pragma unroll
        for (int ni = 0; ni < 8; ni++) {
            int cloc = ni * 8 + 2 * tg;
            float p0 = __expf(s[ni][0] - mn0), p1 = __expf(s[ni][1] - mn0);
            float p2 = __expf(s[ni][2] - mn1), p3 = __expf(s[ni][3] - mn1);
            rs0 += p0 + p1; rs1 += p2 + p3;
            Ps[rg * FPAD + cloc]           = round_tf32(p0);
            Ps[rg * FPAD + cloc + 1]       = round_tf32(p1);
            Ps[(rg + 8) * FPAD + cloc]     = round_tf32(p2);
            Ps[(rg + 8) * FPAD + cloc + 1] = round_tf32(p3);
        }
        rs0 += __shfl_xor_sync(0xffffffffu, rs0, 1);
        rs0 += __shfl_xor_sync(0xffffffffu, rs0, 2);
        rs1 += __shfl_xor_sync(0xffffffffu, rs1, 1);
        rs1 += __shfl_xor_sync(0xffffffffu, rs1, 2);
        l0 = l0 * sc0 + rs0; l1 = l1 * sc1 + rs1;
        m0 = mn0; m1 = mn1;
        #pragma unroll
        for (int ni = 0; ni < 8; ni++) {
            oacc[ni][0] *= sc0; oacc[ni][1] *= sc0;
            oacc[ni][2] *= sc1; oacc[ni][3] *= sc1;
        }
        __syncwarp();

        #pragma unroll
        for (int ki = 0; ki < 8; ++ki) {
            int ak = ki * 8 + tg;
            uint32_t a[4] = { Ps[rg * FPAD + ak],       Ps[(rg + 8) * FPAD + ak],
                              Ps[rg * FPAD + ak + 4],   Ps[(rg + 8) * FPAD + ak + 4] };
            #pragma unroll
            for (int ni = 0; ni < 8; ni++) {
                uint32_t bfr[2] = { Vt[(ni * 8 + g) * FPAD + ak],
                                    Vt[(ni * 8 + g) * FPAD + ak + 4] };
                mma_16n8k8(oacc[ni], a, bfr);
            }
        }
    }

    float inv0 = (l0 > 0.f) ? 1.f / l0 : 0.f;
    float inv1 = (l1 > 0.f) ? 1.f / l1 : 0.f;
    size_t ob0 = ((size_t)b * Sc + qi0) * Dc + h * DHc;
    size_t ob1 = ((size_t)b * Sc + qi1) * Dc + h * DHc;
    #pragma unroll
    for (int ni = 0; ni < 8; ni++) {
        int cc = ni * 8 + 2 * tg;
        *reinterpret_cast<float2*>(&o[ob0 + cc]) = make_float2(oacc[ni][0] * inv0, oacc[ni][1] * inv0);
        *reinterpret_cast<float2*>(&o[ob1 + cc]) = make_float2(oacc[ni][2] * inv1, oacc[ni][3] * inv1);
    }
}

// ---------------- embedding + positional encoding (+ pad mask) ----------------
__global__ void embed_pe_kernel(const int* __restrict__ toks,
                                const float* __restrict__ emb,
                                float* __restrict__ out,
                                unsigned char* __restrict__ mask) {
    int pos = blockIdx.x % Sc;
    int b   = blockIdx.x / Sc;
    int tok = toks[b * Sc + pos];
    int t = threadIdx.x;
    if (t == 0) mask[b * Sc + pos] = (tok == 0) ? 1 : 0;
    const float c = -logf(10000.0f) / (float)Dc;
    size_t base = ((size_t)b * Sc + pos) * Dc;
    #pragma unroll
    for (int d = t; d < Dc; d += 256) {
        int i = d >> 1;
        float freq = __expf((float)(2 * i) * c);
        float ang  = (float)pos * freq;
        float pe   = (d & 1) ? cosf(ang) : sinf(ang);
        out[base + d] = emb[(size_t)tok * Dc + d] + pe;
    }
}

// ---------------- out = LayerNorm(a + b) * gamma + beta ----------------
__global__ void add_ln_kernel(const float* __restrict__ a, const float* __restrict__ bsrc,
                              const float* __restrict__ gamma, const float* __restrict__ beta,
                              float* __restrict__ out) {
    size_t row = blockIdx.x;
    int t = threadIdx.x;
    size_t base = row * Dc;
    float x0 = a[base + t]       + bsrc[base + t];
    float x1 = a[base + t + 256] + bsrc[base + t + 256];
    __shared__ float red[256];
    red[t] = x0 + x1;
    __syncthreads();
    for (int s = 128; s > 0; s >>= 1) { if (t < s) red[t] += red[t + s]; __syncthreads(); }
    float mu = red[0] * (1.0f / Dc);
    __syncthreads();
    float d0 = x0 - mu, d1 = x1 - mu;
    red[t] = d0 * d0 + d1 * d1;
    __syncthreads();
    for (int s = 128; s > 0; s >>= 1) { if (t < s) red[t] += red[t + s]; __syncthreads(); }
    float inv = rsqrtf(red[0] * (1.0f / Dc) + EPSc);
    out[base + t]       = d0 * inv * gamma[t]       + beta[t];
    out[base + t + 256] = d1 * inv * gamma[t + 256] + beta[t + 256];
}

// ---------------- host orchestration ----------------
static void launch_gemm(const float* A, const float* BT, const float* bias, float* C,
                        int M, int N, int K, bool relu) {
    dim3 grid(N / 128, M / 128);
    if (relu) gemm_mma<true ><<<grid, 256, GEMM_SMEM>>>(A, BT, bias, C, M, N, K);
    else      gemm_mma<false><<<grid, 256, GEMM_SMEM>>>(A, BT, bias, C, M, N, K);
}

// self-attention / encoder: fused QKV GEMM (N = 3D). cross: fused KV + separate Q.
static void run_mha(const float* xq, const float* xkv, bool same,
                    const unsigned char* mq, const unsigned char* mk, int causal,
                    const float* wT, const float* b,
                    float* qkvp, float* qsep, float* attnp, float* outp) {
    dim3 gfl(Sc / 128, Bc * NHc);
    if (same) {
        launch_gemm(xq, wT, b, qkvp, BSc, 3 * Dc, Dc, false);
        flash_attn<<<gfl, 256, FLASH_SMEM>>>(qkvp, 3 * Dc, qkvp + Dc, qkvp + 2 * Dc, 3 * Dc,
                                             mq, mk, attnp, causal);
    } else {
        launch_gemm(xq,  wT,               b,      qsep, BSc, Dc,     Dc, false);
        launch_gemm(xkv, wT + (size_t)Dc * Dc, b + Dc, qkvp, BSc, 2 * Dc, Dc, false);
        flash_attn<<<gfl, 256, FLASH_SMEM>>>(qsep, Dc, qkvp, qkvp + Dc, 2 * Dc,
                                             mq, mk, attnp, causal);
    }
    launch_gemm(attnp, wT + 3 * (size_t)Dc * Dc, b + 3 * Dc, outp, BSc, Dc, Dc, false);
}

extern "C" void kernel_launch(void* const* d_in, const int* in_sizes, int n_in,
                              void* d_out, int out_size) {
    const int*   inputs  = (const int*)d_in[0];
    const int*   outputs = (const int*)d_in[1];
    const float* emi = (const float*)d_in[2];
    const float* emo = (const float*)d_in[3];
    const float* enc_attn_w = (const float*)d_in[4];
    const float* enc_attn_b = (const float*)d_in[5];
    const float* enc_ln     = (const float*)d_in[6];
    const float* enc_ffn_w1 = (const float*)d_in[7];
    const float* enc_ffn_b1 = (const float*)d_in[8];
    const float* enc_ffn_w2 = (const float*)d_in[9];
    const float* enc_ffn_b2 = (const float*)d_in[10];
    const float* dec_self_w  = (const float*)d_in[11];
    const float* dec_self_b  = (const float*)d_in[12];
    const float* dec_cross_w = (const float*)d_in[13];
    const float* dec_cross_b = (const float*)d_in[14];
    const float* dec_ln      = (const float*)d_in[15];
    const float* dec_ffn_w1 = (const float*)d_in[16];
    const float* dec_ffn_b1 = (const float*)d_in[17];
    const float* dec_ffn_w2 = (const float*)d_in[18];
    const float* dec_ffn_b2 = (const float*)d_in[19];

    float *xp, *yp, *qp, *attnp, *tmpp, *hidp;
    float *wta_enc, *wta_self, *wta_cross, *wt_ef1, *wt_ef2, *wt_df1, *wt_df2;
    unsigned char *mxp, *myp;
    cudaGetSymbolAddress((void**)&xp, g_x);
    cudaGetSymbolAddress((void**)&yp, g_y);
    cudaGetSymbolAddress((void**)&qp, g_q);
    cudaGetSymbolAddress((void**)&attnp, g_attn);
    cudaGetSymbolAddress((void**)&tmpp, g_tmp);
    cudaGetSymbolAddress((void**)&hidp, g_hid);
    cudaGetSymbolAddress((void**)&mxp, g_mx);
    cudaGetSymbolAddress((void**)&myp, g_my);
    cudaGetSymbolAddress((void**)&wta_enc,   g_wt_enc_attn);
    cudaGetSymbolAddress((void**)&wta_self,  g_wt_dec_self);
    cudaGetSymbolAddress((void**)&wta_cross, g_wt_dec_cross);
    cudaGetSymbolAddress((void**)&wt_ef1, g_wt_enc_f1);
    cudaGetSymbolAddress((void**)&wt_ef2, g_wt_enc_f2);
    cudaGetSymbolAddress((void**)&wt_df1, g_wt_dec_f1);
    cudaGetSymbolAddress((void**)&wt_df2, g_wt_dec_f2);

    cudaFuncSetAttribute(flash_attn, cudaFuncAttributeMaxDynamicSharedMemorySize, FLASH_SMEM);
    cudaFuncSetAttribute(gemm_mma<false>, cudaFuncAttributeMaxDynamicSharedMemorySize, GEMM_SMEM);
    cudaFuncSetAttribute(gemm_mma<true >, cudaFuncAttributeMaxDynamicSharedMemorySize, GEMM_SMEM);

    // -------- weight transposes (tf32-rounded) --------
    dim3 tblk(32, 8);
    transpose_tf32<<<dim3(Dc / 32, Dc / 32, Lc * 4), tblk>>>(enc_attn_w,  wta_enc,   Dc, Dc);
    transpose_tf32<<<dim3(Dc / 32, Dc / 32, Lc * 4), tblk>>>(dec_self_w,  wta_self,  Dc, Dc);
    transpose_tf32<<<dim3(Dc / 32, Dc / 32, Lc * 4), tblk>>>(dec_cross_w, wta_cross, Dc, Dc);
    transpose_tf32<<<dim3(HIDc / 32, Dc / 32, Lc), tblk>>>(enc_ffn_w1, wt_ef1, Dc, HIDc);
    transpose_tf32<<<dim3(Dc / 32, HIDc / 32, Lc), tblk>>>(enc_ffn_w2, wt_ef2, HIDc, Dc);
    transpose_tf32<<<dim3(HIDc / 32, Dc / 32, Lc), tblk>>>(dec_ffn_w1, wt_df1, Dc, HIDc);
    transpose_tf32<<<dim3(Dc / 32, HIDc / 32, Lc), tblk>>>(dec_ffn_w2, wt_df2, HIDc, Dc);

    dim3 blk(256);
    embed_pe_kernel<<<BSc, blk>>>(inputs,  emi, xp, mxp);
    embed_pe_kernel<<<BSc, blk>>>(outputs, emo, yp, myp);

    // ---------------- encoder ----------------
    for (int l = 0; l < Lc; ++l) {
        const float* wT = wta_enc + (size_t)l * 4 * Dc * Dc;
        const float* ab = enc_attn_b + (size_t)l * 4 * Dc;
        run_mha(xp, xp, true, mxp, mxp, 0, wT, ab, hidp, qp, attnp, tmpp);
        const float* ln0 = enc_ln + (((size_t)l * 2 + 0) * 2) * Dc;
        add_ln_kernel<<<BSc, blk>>>(xp, tmpp, ln0, ln0 + Dc, xp);
        launch_gemm(xp, wt_ef1 + (size_t)l * Dc * HIDc, enc_ffn_b1 + (size_t)l * HIDc,
                    hidp, BSc, HIDc, Dc, true);
        launch_gemm(hidp, wt_ef2 + (size_t)l * Dc * HIDc, enc_ffn_b2 + (size_t)l * Dc,
                    tmpp, BSc, Dc, HIDc, false);
        const float* ln1 = enc_ln + (((size_t)l * 2 + 1) * 2) * Dc;
        add_ln_kernel<<<BSc, blk>>>(xp, tmpp, ln1, ln1 + Dc, xp);
    }

    // ---------------- decoder ----------------
    float* fout = (float*)d_out;
    for (int l = 0; l < Lc; ++l) {
        const float* swT = wta_self + (size_t)l * 4 * Dc * Dc;
        const float* sb  = dec_self_b + (size_t)l * 4 * Dc;
        run_mha(yp, yp, true, myp, myp, 1, swT, sb, hidp, qp, attnp, tmpp);
        const float* ln0 = dec_ln + (((size_t)l * 3 + 0) * 2) * Dc;
        add_ln_kernel<<<BSc, blk>>>(yp, tmpp, ln0, ln0 + Dc, yp);

        const float* cwT = wta_cross + (size_t)l * 4 * Dc * Dc;
        const float* cb  = dec_cross_b + (size_t)l * 4 * Dc;
        run_mha(yp, xp, false, myp, mxp, 0, cwT, cb, hidp, qp, attnp, tmpp);
        const float* ln1 = dec_ln + (((size_t)l * 3 + 1) * 2) * Dc;
        add_ln_kernel<<<BSc, blk>>>(yp, tmpp, ln1, ln1 + Dc, yp);

        launch_gemm(yp, wt_df1 + (size_t)l * Dc * HIDc, dec_ffn_b1 + (size_t)l * HIDc,
                    hidp, BSc, HIDc, Dc, true);
        launch_gemm(hidp, wt_df2 + (size_t)l * Dc * HIDc, dec_ffn_b2 + (size_t)l * Dc,
                    tmpp, BSc, Dc, HIDc, false);
        const float* ln2 = dec_ln + (((size_t)l * 3 + 2) * 2) * Dc;
        float* dst = (l == Lc - 1) ? fout : yp;
        add_ln_kernel<<<BSc, blk>>>(yp, tmpp, ln2, ln2 + Dc, dst);
    }
    (void)in_sizes; (void)n_in; (void)out_size;
}

// round 6
// speedup vs baseline: 3.8893x; 1.0734x over previous
#include <cuda_runtime.h>
#include <math.h>
#include <cstdint>

// ---------------- problem constants ----------------
#define Bc   8
#define Sc   512
#define Dc   512
#define NHc  8
#define DHc  64
#define Lc   6
#define HIDc 2048
#define EPSc 1e-5f
#define BSc  (Bc * Sc)          // 4096 tokens
#define SCALEc 0.125f           // 1/sqrt(64)

// ---------------- device scratch ----------------
__device__ float g_x[BSc * Dc];
__device__ float g_y[BSc * Dc];
__device__ float g_q[BSc * Dc];
__device__ float g_attn[BSc * Dc];
__device__ float g_tmp[BSc * Dc];
__device__ float g_hid[BSc * HIDc];      // FFN hidden / fused QKV / fused KV scratch
__device__ unsigned char g_mx[BSc];
__device__ unsigned char g_my[BSc];
// transposed (tf32-rounded) weights: [N][K]
__device__ float g_wt_enc_attn[Lc * 4 * Dc * Dc];
__device__ float g_wt_dec_self[Lc * 4 * Dc * Dc];
__device__ float g_wt_dec_cross[Lc * 4 * Dc * Dc];
__device__ float g_wt_enc_f1[Lc * Dc * HIDc];
__device__ float g_wt_enc_f2[Lc * Dc * HIDc];
__device__ float g_wt_dec_f1[Lc * Dc * HIDc];
__device__ float g_wt_dec_f2[Lc * Dc * HIDc];

__device__ __forceinline__ float neg_inf_f() { return __int_as_float(0xff800000u); }

__device__ __forceinline__ uint32_t round_tf32(float v) {
    uint32_t u; asm("cvt.rna.tf32.f32 %0, %1;" : "=r"(u) : "f"(v)); return u;
}
__device__ __forceinline__ uint32_t smem_u32(const void* p) {
    uint32_t a;
    asm("{ .reg .u64 t; cvta.to.shared.u64 t, %1; cvt.u32.u64 %0, t; }" : "=r"(a) : "l"(p));
    return a;
}

// mma.sync m16n8k8 tf32 (sm_80+ family-compatible; NO tcgen05 on this toolchain)
__device__ __forceinline__ void mma_16n8k8(float c[4], const uint32_t a[4], const uint32_t b[2]) {
    asm volatile(
        "mma.sync.aligned.m16n8k8.row.col.f32.tf32.tf32.f32 "
        "{%0,%1,%2,%3}, {%4,%5,%6,%7}, {%8,%9}, {%0,%1,%2,%3};"
        : "+f"(c[0]), "+f"(c[1]), "+f"(c[2]), "+f"(c[3])
        : "r"(a[0]), "r"(a[1]), "r"(a[2]), "r"(a[3]), "r"(b[0]), "r"(b[1]));
}

// ---------------- weight transpose (with tf32 rounding) ----------------
__global__ void transpose_tf32(const float* __restrict__ in, float* __restrict__ out,
                               int R, int C) {
    __shared__ float tile[32][33];
    const float* src = in + (size_t)blockIdx.z * R * C;
    float* dst = out + (size_t)blockIdx.z * R * C;
    int c0 = blockIdx.x * 32, r0 = blockIdx.y * 32;
    int tx = threadIdx.x, ty = threadIdx.y;          // 32 x 8
    #pragma unroll
    for (int i = 0; i < 32; i += 8)
        tile[ty + i][tx] = src[(size_t)(r0 + ty + i) * C + c0 + tx];
    __syncthreads();
    #pragma unroll
    for (int i = 0; i < 32; i += 8) {
        float v = tile[tx][ty + i];
        dst[(size_t)(c0 + ty + i) * R + r0 + tx] = __uint_as_float(round_tf32(v));
    }
}

// ---------------- tf32 mma GEMM, 3-stage cp.async ring ----------------
// C[M,N] = A[M,K] @ BT[N,K]^T + bias (+ resid). 128x128 CTA tile, 8 warps, K-chunk 32.
#define PADK 36                         // (row*36+k)%32 == (row*4+k)%32 -> conflict-free
#define GBUF (128 * PADK)               // uint32s per operand tile
#define STAGES 3
#define GEMM_SMEM (STAGES * 2 * GBUF * 4)   // 110592 bytes -> 2 CTAs/SM

template<bool RELU>
__global__ void __launch_bounds__(256) gemm_mma(const float* __restrict__ A,
                                                const float* __restrict__ BT,
                                                const float* __restrict__ bias,
                                                const float* __restrict__ resid,
                                                float* __restrict__ C,
                                                int M, int N, int K) {
    extern __shared__ uint32_t gs[];
    uint32_t sbase = smem_u32(gs);
    int tid = threadIdx.x;
    int lane = tid & 31, wid = tid >> 5;
    int wm = wid & 1;
    int wn = wid >> 1;
    int row0 = blockIdx.y * 128, col0 = blockIdx.x * 128;
    int g = lane >> 2, tg = lane & 3;
    int lr = tid >> 3, lc = (tid & 7) * 4;

    float acc[4][4][4];
    #pragma unroll
    for (int mi = 0; mi < 4; mi++)
        #pragma unroll
        for (int ni = 0; ni < 4; ni++)
            #pragma unroll
            for (int r = 0; r < 4; r++) acc[mi][ni][r] = 0.0f;

    int nch = K >> 5;

    // prefetch chunk 0 into stage 0
    {
        uint32_t abase = sbase;
        uint32_t bbase = sbase + GBUF * 4;
        #pragma unroll
        for (int i = 0; i < 4; ++i) {
            int r = lr + i * 32;
            uint32_t off = (uint32_t)(r * PADK + lc) * 4;
            const float* pa = &A[(size_t)(row0 + r) * K + lc];
            asm volatile("cp.async.cg.shared.global [%0], [%1], 16;" :: "r"(abase + off), "l"(pa));
            const float* pb = &BT[(size_t)(col0 + r) * K + lc];
            asm volatile("cp.async.cg.shared.global [%0], [%1], 16;" :: "r"(bbase + off), "l"(pb));
        }
        asm volatile("cp.async.commit_group;" ::: "memory");
    }

    for (int c = 0; c < nch; ++c) {
        // depth-1 prefetch: chunk c+1 into stage (c+1)%3.
        // Stage (c+1)%3 was last computed at iter c-2; the barrier at iter c-1
        // (passed by every warp before any warp reaches this point) makes the
        // overwrite safe with a single barrier per iteration.
        if (c + 1 < nch) {
            int k0 = (c + 1) << 5;
            uint32_t abase = sbase + (uint32_t)(((c + 1) % STAGES) * 2 * GBUF) * 4;
            uint32_t bbase = abase + GBUF * 4;
            #pragma unroll
            for (int i = 0; i < 4; ++i) {
                int r = lr + i * 32;
                uint32_t off = (uint32_t)(r * PADK + lc) * 4;
                const float* pa = &A[(size_t)(row0 + r) * K + k0 + lc];
                asm volatile("cp.async.cg.shared.global [%0], [%1], 16;" :: "r"(abase + off), "l"(pa));
                const float* pb = &BT[(size_t)(col0 + r) * K + k0 + lc];
                asm volatile("cp.async.cg.shared.global [%0], [%1], 16;" :: "r"(bbase + off), "l"(pb));
            }
        }
        asm volatile("cp.async.commit_group;" ::: "memory");   // empty group ok on last iter
        asm volatile("cp.async.wait_group 1;" ::: "memory");   // chunk c landed
        __syncthreads();

        const uint32_t* As = gs + (c % STAGES) * 2 * GBUF;
        const uint32_t* Bs = As + GBUF;

        #pragma unroll
        for (int ki = 0; ki < 4; ++ki) {
            int ak = ki * 8 + tg;
            uint32_t afr[4][4];
            #pragma unroll
            for (int mi = 0; mi < 4; mi++) {
                int r = wm * 64 + mi * 16 + g;
                afr[mi][0] = round_tf32(__uint_as_float(As[(r)     * PADK + ak]));
                afr[mi][1] = round_tf32(__uint_as_float(As[(r + 8) * PADK + ak]));
                afr[mi][2] = round_tf32(__uint_as_float(As[(r)     * PADK + ak + 4]));
                afr[mi][3] = round_tf32(__uint_as_float(As[(r + 8) * PADK + ak + 4]));
            }
            uint32_t bfr[4][2];
            #pragma unroll
            for (int ni = 0; ni < 4; ni++) {
                int n = wn * 32 + ni * 8 + g;
                bfr[ni][0] = Bs[n * PADK + ak];
                bfr[ni][1] = Bs[n * PADK + ak + 4];
            }
            #pragma unroll
            for (int mi = 0; mi < 4; mi++)
                #pragma unroll
                for (int ni = 0; ni < 4; ni++)
                    mma_16n8k8(acc[mi][ni], afr[mi], bfr[ni]);
        }
        // no trailing barrier: next iteration's single barrier provides ordering
    }

    #pragma unroll
    for (int mi = 0; mi < 4; mi++) {
        int r0r = row0 + wm * 64 + mi * 16 + g;
        #pragma unroll
        for (int ni = 0; ni < 4; ni++) {
            int cb = col0 + wn * 32 + ni * 8 + tg * 2;
            float b0 = bias[cb], b1 = bias[cb + 1];
            float v0 = acc[mi][ni][0] + b0, v1 = acc[mi][ni][1] + b1;
            float v2 = acc[mi][ni][2] + b0, v3 = acc[mi][ni][3] + b1;
            if (resid) {
                float2 r0v = *reinterpret_cast<const float2*>(&resid[(size_t)(r0r)     * N + cb]);
                float2 r1v = *reinterpret_cast<const float2*>(&resid[(size_t)(r0r + 8) * N + cb]);
                v0 += r0v.x; v1 += r0v.y; v2 += r1v.x; v3 += r1v.y;
            }
            if (RELU) { v0 = fmaxf(v0, 0.f); v1 = fmaxf(v1, 0.f);
                        v2 = fmaxf(v2, 0.f); v3 = fmaxf(v3, 0.f); }
            *reinterpret_cast<float2*>(&C[(size_t)(r0r)     * N + cb]) = make_float2(v0, v1);
            *reinterpret_cast<float2*>(&C[(size_t)(r0r + 8) * N + cb]) = make_float2(v2, v3);
        }
    }
}

// ---------------- fused flash attention (tf32 mma), strided q/k/v ----------------
#define FPAD 68
#define FLASH_SMEM ((128 + 64 + 64 + 128) * FPAD * 4 + 64)

__global__ void __launch_bounds__(256) flash_attn(
    const float* __restrict__ q, int ldq,
    const float* __restrict__ k, const float* __restrict__ v, int ldkv,
    const unsigned char* __restrict__ mqg, const unsigned char* __restrict__ mkg,
    float* __restrict__ o, int causal)
{
    extern __shared__ char sm[];
    uint32_t* Qs = reinterpret_cast<uint32_t*>(sm);
    uint32_t* Ks = Qs + 128 * FPAD;
    uint32_t* Vt = Ks + 64 * FPAD;
    uint32_t* Ps = Vt + 64 * FPAD;
    unsigned char* mks = reinterpret_cast<unsigned char*>(Ps + 128 * FPAD);

    int tid = threadIdx.x, lane = tid & 31, wid = tid >> 5;
    int bh = blockIdx.y, b = bh >> 3, h = bh & 7;
    int q0 = blockIdx.x * 128;
    const float* Qg = q + (size_t)b * Sc * ldq + h * DHc;
    const float* Kg = k + (size_t)b * Sc * ldkv + h * DHc;
    const float* Vg = v + (size_t)b * Sc * ldkv + h * DHc;
    int g = lane >> 2, tg = lane & 3;
    int rg = wid * 16 + g;
    int qi0 = q0 + rg, qi1 = qi0 + 8;

    #pragma unroll
    for (int i = 0; i < 8; ++i) {
        int idx = tid + i * 256;
        int r = idx >> 4, c = (idx & 15) * 4;
        float4 va = *reinterpret_cast<const float4*>(&Qg[(size_t)(q0 + r) * ldq + c]);
        Qs[r * FPAD + c + 0] = round_tf32(va.x);
        Qs[r * FPAD + c + 1] = round_tf32(va.y);
        Qs[r * FPAD + c + 2] = round_tf32(va.z);
        Qs[r * FPAD + c + 3] = round_tf32(va.w);
    }
    bool mrow0 = mqg[b * Sc + qi0] != 0;
    bool mrow1 = mqg[b * Sc + qi1] != 0;

    float m0 = -1e30f, m1 = -1e30f, l0 = 0.f, l1 = 0.f;
    float oacc[8][4];
    #pragma unroll
    for (int ni = 0; ni < 8; ni++) { oacc[ni][0] = oacc[ni][1] = oacc[ni][2] = oacc[ni][3] = 0.f; }

    int nkt = causal ? ((q0 >> 6) + 2) : (Sc / 64);
    for (int kt = 0; kt < nkt; ++kt) {
        int k0 = kt * 64;
        __syncthreads();
        #pragma unroll
        for (int i = 0; i < 4; ++i) {
            int idx = tid + i * 256;
            int r = idx >> 4, c = (idx & 15) * 4;
            float4 vk = *reinterpret_cast<const float4*>(&Kg[(size_t)(k0 + r) * ldkv + c]);
            Ks[r * FPAD + c + 0] = round_tf32(vk.x);
            Ks[r * FPAD + c + 1] = round_tf32(vk.y);
            Ks[r * FPAD + c + 2] = round_tf32(vk.z);
            Ks[r * FPAD + c + 3] = round_tf32(vk.w);
            float4 vv = *reinterpret_cast<const float4*>(&Vg[(size_t)(k0 + r) * ldkv + c]);
            Vt[(c + 0) * FPAD + r] = round_tf32(vv.x);
            Vt[(c + 1) * FPAD + r] = round_tf32(vv.y);
            Vt[(c + 2) * FPAD + r] = round_tf32(vv.z);
            Vt[(c + 3) * FPAD + r] = round_tf32(vv.w);
        }
        if (tid < 64) mks[tid] = mkg[b * Sc + k0 + tid];
        __syncthreads();

        float s[8][4];
        #pragma unroll
        for (int ni = 0; ni < 8; ni++) { s[ni][0] = s[ni][1] = s[ni][2] = s[ni][3] = 0.f; }
        #pragma unroll
        for (int ki = 0; ki < 8; ++ki) {
            int ak = ki * 8 + tg;
            uint32_t a[4] = { Qs[rg * FPAD + ak],       Qs[(rg + 8) * FPAD + ak],
                              Qs[rg * FPAD + ak + 4],   Qs[(rg + 8) * FPAD + ak + 4] };
            #pragma unroll
            for (int ni = 0; ni < 8; ni++) {
                uint32_t bfr[2] = { Ks[(ni * 8 + g) * FPAD + ak],
                                    Ks[(ni * 8 + g) * FPAD + ak + 4] };
                mma_16n8k8(s[ni], a, bfr);
            }
        }

        float rmax0 = neg_inf_f(), rmax1 = neg_inf_f();
        #pragma unroll
        for (int ni = 0; ni < 8; ni++) {
            int cloc = ni * 8 + 2 * tg;
            int cg = k0 + cloc;
            bool mkA = mks[cloc] != 0, mkB = mks[cloc + 1] != 0;
            float v0 = (mrow0 || mkA || (causal && cg     > qi0)) ? neg_inf_f() : s[ni][0] * SCALEc;
            float v1 = (mrow0 || mkB || (causal && cg + 1 > qi0)) ? neg_inf_f() : s[ni][1] * SCALEc;
            float v2 = (mrow1 || mkA || (causal && cg     > qi1)) ? neg_inf_f() : s[ni][2] * SCALEc;
            float v3 = (mrow1 || mkB || (causal && cg + 1 > qi1)) ? neg_inf_f() : s[ni][3] * SCALEc;
            s[ni][0] = v0; s[ni][1] = v1; s[ni][2] = v2; s[ni][3] = v3;
            rmax0 = fmaxf(rmax0, fmaxf(v0, v1));
            rmax1 = fmaxf(rmax1, fmaxf(v2, v3));
        }
        rmax0 = fmaxf(rmax0, __shfl_xor_sync(0xffffffffu, rmax0, 1));
        rmax0 = fmaxf(rmax0, __shfl_xor_sync(0xffffffffu, rmax0, 2));
        rmax1 = fmaxf(rmax1, __shfl_xor_sync(0xffffffffu, rmax1, 1));
        rmax1 = fmaxf(rmax1, __shfl_xor_sync(0xffffffffu, rmax1, 2));

        float mn0 = fmaxf(m0, rmax0), mn1 = fmaxf(m1, rmax1);
        float sc0 = __expf(m0 - mn0), sc1 = __expf(m1 - mn1);
        float rs0 = 0.f, rs1 = 0.f;
        #pragma unroll
        for (int ni = 0; ni < 8; ni++) {
            int cloc = ni * 8 + 2 * tg;
            float p0 = __expf(s[ni][0] - mn0), p1 = __expf(s[ni][1] - mn0);
            float p2 = __expf(s[ni][2] - mn1), p3 = __expf(s[ni][3] - mn1);
            rs0 += p0 + p1; rs1 += p2 + p3;
            Ps[rg * FPAD + cloc]           = round_tf32(p0);
            Ps[rg * FPAD + cloc + 1]       = round_tf32(p1);
            Ps[(rg + 8) * FPAD + cloc]     = round_tf32(p2);
            Ps[(rg + 8) * FPAD + cloc + 1] = round_tf32(p3);
        }
        rs0 += __shfl_xor_sync(0xffffffffu, rs0, 1);
        rs0 += __shfl_xor_sync(0xffffffffu, rs0, 2);
        rs1 += __shfl_xor_sync(0xffffffffu, rs1, 1);
        rs1 += __shfl_xor_sync(0xffffffffu, rs1, 2);
        l0 = l0 * sc0 + rs0; l1 = l1 * sc1 + rs1;
        m0 = mn0; m1 = mn1;
        #pragma unroll
        for (int ni = 0; ni < 8; ni++) {
            oacc[ni][0] *= sc0; oacc[ni][1] *= sc0;
            oacc[ni][2] *= sc1; oacc[ni][3] *= sc1;
        }
        __syncwarp();

        #pragma unroll
        for (int ki = 0; ki < 8; ++ki) {
            int ak = ki * 8 + tg;
            uint32_t a[4] = { Ps[rg * FPAD + ak],       Ps[(rg + 8) * FPAD + ak],
                              Ps[rg * FPAD + ak + 4],   Ps[(rg + 8) * FPAD + ak + 4] };
            #pragma unroll
            for (int ni = 0; ni < 8; ni++) {
                uint32_t bfr[2] = { Vt[(ni * 8 + g) * FPAD + ak],
                                    Vt[(ni * 8 + g) * FPAD + ak + 4] };
                mma_16n8k8(oacc[ni], a, bfr);
            }
        }
    }

    float inv0 = (l0 > 0.f) ? 1.f / l0 : 0.f;
    float inv1 = (l1 > 0.f) ? 1.f / l1 : 0.f;
    size_t ob0 = ((size_t)b * Sc + qi0) * Dc + h * DHc;
    size_t ob1 = ((size_t)b * Sc + qi1) * Dc + h * DHc;
    #pragma unroll
    for (int ni = 0; ni < 8; ni++) {
        int cc = ni * 8 + 2 * tg;
        *reinterpret_cast<float2*>(&o[ob0 + cc]) = make_float2(oacc[ni][0] * inv0, oacc[ni][1] * inv0);
        *reinterpret_cast<float2*>(&o[ob1 + cc]) = make_float2(oacc[ni][2] * inv1, oacc[ni][3] * inv1);
    }
}

// ---------------- embedding + positional encoding (+ pad mask) ----------------
__global__ void embed_pe_kernel(const int* __restrict__ toks,
                                const float* __restrict__ emb,
                                float* __restrict__ out,
                                unsigned char* __restrict__ mask) {
    int pos = blockIdx.x % Sc;
    int b   = blockIdx.x / Sc;
    int tok = toks[b * Sc + pos];
    int t = threadIdx.x;
    if (t == 0) mask[b * Sc + pos] = (tok == 0) ? 1 : 0;
    const float c = -logf(10000.0f) / (float)Dc;
    size_t base = ((size_t)b * Sc + pos) * Dc;
    #pragma unroll
    for (int d = t; d < Dc; d += 256) {
        int i = d >> 1;
        float freq = __expf((float)(2 * i) * c);
        float ang  = (float)pos * freq;
        float pe   = (d & 1) ? cosf(ang) : sinf(ang);
        out[base + d] = emb[(size_t)tok * Dc + d] + pe;
    }
}

// ---------------- out = LayerNorm(xin) * gamma + beta  (warp per row) ----------------
__global__ void __launch_bounds__(256) ln_kernel(const float* __restrict__ xin,
                                                 const float* __restrict__ gamma,
                                                 const float* __restrict__ beta,
                                                 float* __restrict__ out) {
    int warp = threadIdx.x >> 5, lane = threadIdx.x & 31;
    size_t row = (size_t)blockIdx.x * 8 + warp;
    size_t base = row * Dc;
    float4 v[4];
    float sum = 0.f;
    #pragma unroll
    for (int i = 0; i < 4; ++i) {
        v[i] = *reinterpret_cast<const float4*>(&xin[base + lane * 4 + i * 128]);
        sum += v[i].x + v[i].y + v[i].z + v[i].w;
    }
    #pragma unroll
    for (int s = 16; s > 0; s >>= 1) sum += __shfl_xor_sync(0xffffffffu, sum, s);
    float mu = sum * (1.0f / Dc);
    float var = 0.f;
    #pragma unroll
    for (int i = 0; i < 4; ++i) {
        v[i].x -= mu; v[i].y -= mu; v[i].z -= mu; v[i].w -= mu;
        var += v[i].x * v[i].x + v[i].y * v[i].y + v[i].z * v[i].z + v[i].w * v[i].w;
    }
    #pragma unroll
    for (int s = 16; s > 0; s >>= 1) var += __shfl_xor_sync(0xffffffffu, var, s);
    float inv = rsqrtf(var * (1.0f / Dc) + EPSc);
    #pragma unroll
    for (int i = 0; i < 4; ++i) {
        int col = lane * 4 + i * 128;
        float4 gv = *reinterpret_cast<const float4*>(&gamma[col]);
        float4 bv = *reinterpret_cast<const float4*>(&beta[col]);
        float4 o;
        o.x = v[i].x * inv * gv.x + bv.x;
        o.y = v[i].y * inv * gv.y + bv.y;
        o.z = v[i].z * inv * gv.z + bv.z;
        o.w = v[i].w * inv * gv.w + bv.w;
        *reinterpret_cast<float4*>(&out[base + col]) = o;
    }
}

// ---------------- host orchestration ----------------
static void launch_gemm(const float* A, const float* BT, const float* bias,
                        const float* resid, float* C, int M, int N, int K, bool relu) {
    dim3 grid(N / 128, M / 128);
    if (relu) gemm_mma<true ><<<grid, 256, GEMM_SMEM>>>(A, BT, bias, resid, C, M, N, K);
    else      gemm_mma<false><<<grid, 256, GEMM_SMEM>>>(A, BT, bias, resid, C, M, N, K);
}

// out-proj epilogue fuses the residual; caller then runs single-input LN.
static void run_mha(const float* xq, const float* xkv, bool same,
                    const unsigned char* mq, const unsigned char* mk, int causal,
                    const float* wT, const float* b, const float* resid,
                    float* qkvp, float* qsep, float* attnp, float* outp) {
    dim3 gfl(Sc / 128, Bc * NHc);
    if (same) {
        launch_gemm(xq, wT, b, nullptr, qkvp, BSc, 3 * Dc, Dc, false);
        flash_attn<<<gfl, 256, FLASH_SMEM>>>(qkvp, 3 * Dc, qkvp + Dc, qkvp + 2 * Dc, 3 * Dc,
                                             mq, mk, attnp, causal);
    } else {
        launch_gemm(xq,  wT,                   b,      nullptr, qsep, BSc, Dc,     Dc, false);
        launch_gemm(xkv, wT + (size_t)Dc * Dc, b + Dc, nullptr, qkvp, BSc, 2 * Dc, Dc, false);
        flash_attn<<<gfl, 256, FLASH_SMEM>>>(qsep, Dc, qkvp, qkvp + Dc, 2 * Dc,
                                             mq, mk, attnp, causal);
    }
    launch_gemm(attnp, wT + 3 * (size_t)Dc * Dc, b + 3 * Dc, resid, outp, BSc, Dc, Dc, false);
}

extern "C" void kernel_launch(void* const* d_in, const int* in_sizes, int n_in,
                              void* d_out, int out_size) {
    const int*   inputs  = (const int*)d_in[0];
    const int*   outputs = (const int*)d_in[1];
    const float* emi = (const float*)d_in[2];
    const float* emo = (const float*)d_in[3];
    const float* enc_attn_w = (const float*)d_in[4];
    const float* enc_attn_b = (const float*)d_in[5];
    const float* enc_ln     = (const float*)d_in[6];
    const float* enc_ffn_w1 = (const float*)d_in[7];
    const float* enc_ffn_b1 = (const float*)d_in[8];
    const float* enc_ffn_w2 = (const float*)d_in[9];
    const float* enc_ffn_b2 = (const float*)d_in[10];
    const float* dec_self_w  = (const float*)d_in[11];
    const float* dec_self_b  = (const float*)d_in[12];
    const float* dec_cross_w = (const float*)d_in[13];
    const float* dec_cross_b = (const float*)d_in[14];
    const float* dec_ln      = (const float*)d_in[15];
    const float* dec_ffn_w1 = (const float*)d_in[16];
    const float* dec_ffn_b1 = (const float*)d_in[17];
    const float* dec_ffn_w2 = (const float*)d_in[18];
    const float* dec_ffn_b2 = (const float*)d_in[19];

    float *xp, *yp, *qp, *attnp, *tmpp, *hidp;
    float *wta_enc, *wta_self, *wta_cross, *wt_ef1, *wt_ef2, *wt_df1, *wt_df2;
    unsigned char *mxp, *myp;
    cudaGetSymbolAddress((void**)&xp, g_x);
    cudaGetSymbolAddress((void**)&yp, g_y);
    cudaGetSymbolAddress((void**)&qp, g_q);
    cudaGetSymbolAddress((void**)&attnp, g_attn);
    cudaGetSymbolAddress((void**)&tmpp, g_tmp);
    cudaGetSymbolAddress((void**)&hidp, g_hid);
    cudaGetSymbolAddress((void**)&mxp, g_mx);
    cudaGetSymbolAddress((void**)&myp, g_my);
    cudaGetSymbolAddress((void**)&wta_enc,   g_wt_enc_attn);
    cudaGetSymbolAddress((void**)&wta_self,  g_wt_dec_self);
    cudaGetSymbolAddress((void**)&wta_cross, g_wt_dec_cross);
    cudaGetSymbolAddress((void**)&wt_ef1, g_wt_enc_f1);
    cudaGetSymbolAddress((void**)&wt_ef2, g_wt_enc_f2);
    cudaGetSymbolAddress((void**)&wt_df1, g_wt_dec_f1);
    cudaGetSymbolAddress((void**)&wt_df2, g_wt_dec_f2);

    cudaFuncSetAttribute(flash_attn, cudaFuncAttributeMaxDynamicSharedMemorySize, FLASH_SMEM);
    cudaFuncSetAttribute(gemm_mma<false>, cudaFuncAttributeMaxDynamicSharedMemorySize, GEMM_SMEM);
    cudaFuncSetAttribute(gemm_mma<true >, cudaFuncAttributeMaxDynamicSharedMemorySize, GEMM_SMEM);

    // -------- weight transposes (tf32-rounded) --------
    dim3 tblk(32, 8);
    transpose_tf32<<<dim3(Dc / 32, Dc / 32, Lc * 4), tblk>>>(enc_attn_w,  wta_enc,   Dc, Dc);
    transpose_tf32<<<dim3(Dc / 32, Dc / 32, Lc * 4), tblk>>>(dec_self_w,  wta_self,  Dc, Dc);
    transpose_tf32<<<dim3(Dc / 32, Dc / 32, Lc * 4), tblk>>>(dec_cross_w, wta_cross, Dc, Dc);
    transpose_tf32<<<dim3(HIDc / 32, Dc / 32, Lc), tblk>>>(enc_ffn_w1, wt_ef1, Dc, HIDc);
    transpose_tf32<<<dim3(Dc / 32, HIDc / 32, Lc), tblk>>>(enc_ffn_w2, wt_ef2, HIDc, Dc);
    transpose_tf32<<<dim3(HIDc / 32, Dc / 32, Lc), tblk>>>(dec_ffn_w1, wt_df1, Dc, HIDc);
    transpose_tf32<<<dim3(Dc / 32, HIDc / 32, Lc), tblk>>>(dec_ffn_w2, wt_df2, HIDc, Dc);

    dim3 blk(256);
    embed_pe_kernel<<<BSc, blk>>>(inputs,  emi, xp, mxp);
    embed_pe_kernel<<<BSc, blk>>>(outputs, emo, yp, myp);

    int lng = BSc / 8;   // 512 blocks, warp per row

    // ---------------- encoder ----------------
    for (int l = 0; l < Lc; ++l) {
        const float* wT = wta_enc + (size_t)l * 4 * Dc * Dc;
        const float* ab = enc_attn_b + (size_t)l * 4 * Dc;
        run_mha(xp, xp, true, mxp, mxp, 0, wT, ab, xp, hidp, qp, attnp, tmpp);
        const float* ln0 = enc_ln + (((size_t)l * 2 + 0) * 2) * Dc;
        ln_kernel<<<lng, blk>>>(tmpp, ln0, ln0 + Dc, xp);
        launch_gemm(xp, wt_ef1 + (size_t)l * Dc * HIDc, enc_ffn_b1 + (size_t)l * HIDc,
                    nullptr, hidp, BSc, HIDc, Dc, true);
        launch_gemm(hidp, wt_ef2 + (size_t)l * Dc * HIDc, enc_ffn_b2 + (size_t)l * Dc,
                    xp, tmpp, BSc, Dc, HIDc, false);
        const float* ln1 = enc_ln + (((size_t)l * 2 + 1) * 2) * Dc;
        ln_kernel<<<lng, blk>>>(tmpp, ln1, ln1 + Dc, xp);
    }

    // ---------------- decoder ----------------
    float* fout = (float*)d_out;
    for (int l = 0; l < Lc; ++l) {
        const float* swT = wta_self + (size_t)l * 4 * Dc * Dc;
        const float* sb  = dec_self_b + (size_t)l * 4 * Dc;
        run_mha(yp, yp, true, myp, myp, 1, swT, sb, yp, hidp, qp, attnp, tmpp);
        const float* ln0 = dec_ln + (((size_t)l * 3 + 0) * 2) * Dc;
        ln_kernel<<<lng, blk>>>(tmpp, ln0, ln0 + Dc, yp);

        const float* cwT = wta_cross + (size_t)l * 4 * Dc * Dc;
        const float* cb  = dec_cross_b + (size_t)l * 4 * Dc;
        run_mha(yp, xp, false, myp, mxp, 0, cwT, cb, yp, hidp, qp, attnp, tmpp);
        const float* ln1 = dec_ln + (((size_t)l * 3 + 1) * 2) * Dc;
        ln_kernel<<<lng, blk>>>(tmpp, ln1, ln1 + Dc, yp);

        launch_gemm(yp, wt_df1 + (size_t)l * Dc * HIDc, dec_ffn_b1 + (size_t)l * HIDc,
                    nullptr, hidp, BSc, HIDc, Dc, true);
        launch_gemm(hidp, wt_df2 + (size_t)l * Dc * HIDc, dec_ffn_b2 + (size_t)l * Dc,
                    yp, tmpp, BSc, Dc, HIDc, false);
        const float* ln2 = dec_ln + (((size_t)l * 3 + 2) * 2) * Dc;
        float* dst = (l == Lc - 1) ? fout : yp;
        ln_kernel<<<lng, blk>>>(tmpp, ln2, ln2 + Dc, dst);
    }
    (void)in_sizes; (void)n_in; (void)out_size;
}